// round 1
// baseline (speedup 1.0000x reference)
#include <cuda_runtime.h>
#include <cuda_bf16.h>
#include <cstdint>

// Problem constants
constexpr int BB = 4;
constexpr int LL = 4096;
constexpr int DD = 1024;
constexpr int FFD = 2048;
constexpr int TT = 32;              // scan chunk length
constexpr int CC = LL / TT;         // 128 chunks
constexpr int MROWS = BB * LL;      // 16384
constexpr float EPS = 1e-5f;

// ---------------- scratch (device globals; no runtime allocation) ----------
__device__ float  g_conv[BB * LL * DD];
__device__ float  g_x2  [BB * LL * DD];
__device__ float  g_hid [(size_t)BB * LL * FFD];
__device__ float2 g_st1 [BB * LL];
__device__ float2 g_st2 [BB * LL];
__device__ float2 g_cv  [BB * CC * DD];
__device__ float2 g_carry[BB * CC * DD];

// ---------------- helpers ---------------------------------------------------
__device__ __forceinline__ float tf32r(float x) {
    uint32_t u;
    asm("cvt.rna.tf32.f32 %0, %1;" : "=r"(u) : "f"(x));
    return __uint_as_float(u);
}

__device__ __forceinline__ float silu(float v) {
    return v / (1.0f + expf(-v));
}

__device__ __forceinline__ void mma8(float* c, const uint32_t* a, const uint32_t* b) {
    asm volatile(
        "mma.sync.aligned.m16n8k8.row.col.f32.tf32.tf32.f32 "
        "{%0,%1,%2,%3}, {%4,%5,%6,%7}, {%8,%9}, {%0,%1,%2,%3};\n"
        : "+f"(c[0]), "+f"(c[1]), "+f"(c[2]), "+f"(c[3])
        : "r"(a[0]), "r"(a[1]), "r"(a[2]), "r"(a[3]), "r"(b[0]), "r"(b[1]));
}

// ---------------- LayerNorm row stats ---------------------------------------
__device__ __forceinline__ void stats_body(const float* __restrict__ src,
                                           float2* __restrict__ dst) {
    int row = blockIdx.x;
    int tid = threadIdx.x;          // 256 threads, 4 floats each = 1024
    float4 v = *(const float4*)(src + (size_t)row * DD + tid * 4);
    float s = v.x + v.y + v.z + v.w;
    float q = v.x * v.x + v.y * v.y + v.z * v.z + v.w * v.w;
#pragma unroll
    for (int o = 16; o; o >>= 1) {
        s += __shfl_xor_sync(0xffffffffu, s, o);
        q += __shfl_xor_sync(0xffffffffu, q, o);
    }
    __shared__ float2 ws[8];
    if ((tid & 31) == 0) ws[tid >> 5] = make_float2(s, q);
    __syncthreads();
    if (tid < 8) {
        float ss = ws[tid].x, qq = ws[tid].y;
#pragma unroll
        for (int o = 4; o; o >>= 1) {
            ss += __shfl_xor_sync(0xffu, ss, o);
            qq += __shfl_xor_sync(0xffu, qq, o);
        }
        if (tid == 0) {
            float mean = ss * (1.0f / DD);
            float var  = qq * (1.0f / DD) - mean * mean;
            dst[row] = make_float2(mean, rsqrtf(var + EPS));
        }
    }
}

__global__ void k_stats1(const float* __restrict__ x) { stats_body(x, g_st1); }
__global__ void k_stats2()                            { stats_body(g_x2, g_st2); }

// ---------------- spiral-conv scan ------------------------------------------
// c[t] = phz*c[t-1] + phi*xn[t],  c[-1] = lci,  phz = ph/|ph| * exp(-|ph|)

template <bool PHASE3>
__global__ void __launch_bounds__(1024) k_scan(
    const float* __restrict__ x,
    const float* __restrict__ phre, const float* __restrict__ phim,
    const float* __restrict__ phir, const float* __restrict__ phii,
    const float* __restrict__ lng,  const float* __restrict__ lnb) {
    int d = threadIdx.x;
    int j = blockIdx.x;   // chunk
    int b = blockIdx.y;   // batch

    float pre = phre[d], pim = phim[d];
    float a  = sqrtf(pre * pre + pim * pim);
    float sc = expf(-a) / a;
    float pzr = pre * sc, pzi = pim * sc;
    float fr = phir[d], fi = phii[d];
    float g = lng[d], bbv = lnb[d];

    size_t rowbase = (size_t)b * LL + (size_t)j * TT;
    float cr, ci;
    if (PHASE3) {
        float2 cc = g_carry[((size_t)b * CC + j) * DD + d];
        cr = cc.x; ci = cc.y;
    } else {
        cr = 0.0f; ci = 0.0f;
    }
    const float* xp = x + rowbase * DD + d;
#pragma unroll 4
    for (int s = 0; s < TT; s++) {
        float2 st = g_st1[rowbase + s];
        float xv = xp[(size_t)s * DD];
        float xn = (xv - st.x) * st.y * g + bbv;
        float nr = cr * pzr - ci * pzi + fr * xn;
        float ni = cr * pzi + ci * pzr + fi * xn;
        cr = nr; ci = ni;
        if (PHASE3) g_conv[rowbase * DD + (size_t)s * DD + d] = cr;
    }
    if (!PHASE3) g_cv[((size_t)b * CC + j) * DD + d] = make_float2(cr, ci);
}

__global__ void k_scan2(const float* __restrict__ phre, const float* __restrict__ phim,
                        const float* __restrict__ lcire, const float* __restrict__ lciim) {
    int idx = blockIdx.x * blockDim.x + threadIdx.x;   // BB*DD threads
    int b = idx / DD, d = idx % DD;
    float pre = phre[d], pim = phim[d];
    float a  = sqrtf(pre * pre + pim * pim);
    float sc = expf(-a) / a;
    float tr = pre * sc, ti = pim * sc;
    // phz^TT, TT = 32 = 2^5 -> 5 complex squarings
#pragma unroll
    for (int i = 0; i < 5; i++) {
        float nr = tr * tr - ti * ti;
        ti = 2.0f * tr * ti;
        tr = nr;
    }
    float cr = lcire[d], ci = lciim[d];
    g_carry[((size_t)b * CC + 0) * DD + d] = make_float2(cr, ci);
    for (int jj = 0; jj < CC - 1; jj++) {
        float2 v = g_cv[((size_t)b * CC + jj) * DD + d];
        float nr = tr * cr - ti * ci + v.x;
        float ni = tr * ci + ti * cr + v.y;
        cr = nr; ci = ni;
        g_carry[((size_t)b * CC + jj + 1) * DD + d] = make_float2(cr, ci);
    }
}

// ---------------- tf32 tensor-core GEMM -------------------------------------
// C = A[M,K] @ W[K,N]; BM=BN=128, BK=32; 256 threads, 8 warps of 32x64.
// EPI 0: out = silu(acc+bias)
// EPI 1: out = conv * silu(acc+bias) + xres      (x2 for GEMM1)
// EPI 2: out = acc + bias + xres                 (final residual)
// LNA: apply LayerNorm to A elements on tile load (stats + lng/lnb).

template <int EPI, bool LNA>
__device__ __forceinline__ void gemm_body(
    const float* __restrict__ A, const float* __restrict__ W,
    const float* __restrict__ bias,
    int N, int K,
    const float2* __restrict__ stats,
    const float* __restrict__ lng, const float* __restrict__ lnb,
    const float* __restrict__ conv, const float* __restrict__ xres,
    float* __restrict__ out) {
    __shared__ float As[128][36];
    __shared__ float Bs[32][136];

    int tid = threadIdx.x;
    int lane = tid & 31, wid = tid >> 5;
    int warp_m = wid >> 1;      // 0..3  (32-row slabs)
    int warp_n = wid & 1;       // 0..1  (64-col slabs)
    int grp = lane >> 2, tig = lane & 3;
    int bm = blockIdx.y, bn = blockIdx.x;

    float acc[2][8][4];
#pragma unroll
    for (int mt = 0; mt < 2; mt++)
#pragma unroll
        for (int nt = 0; nt < 8; nt++)
#pragma unroll
            for (int i = 0; i < 4; i++) acc[mt][nt][i] = 0.0f;

    int ar0 = tid >> 3, ac4 = (tid & 7) * 4;       // A loader: 32 rows/pass
    int br0 = tid >> 5, bc4 = (tid & 31) * 4;      // B loader: 8 rows/pass

    for (int kt = 0; kt < K; kt += 32) {
        // ---- load A tile (with optional fused LayerNorm) ----
#pragma unroll
        for (int i = 0; i < 4; i++) {
            int r = ar0 + i * 32;
            int grow = bm * 128 + r;
            float4 v = *(const float4*)(A + (size_t)grow * K + kt + ac4);
            if (LNA) {
                float2 st = stats[grow];
                float4 gg = *(const float4*)(lng + kt + ac4);
                float4 bb = *(const float4*)(lnb + kt + ac4);
                v.x = (v.x - st.x) * st.y * gg.x + bb.x;
                v.y = (v.y - st.x) * st.y * gg.y + bb.y;
                v.z = (v.z - st.x) * st.y * gg.z + bb.z;
                v.w = (v.w - st.x) * st.y * gg.w + bb.w;
            }
            v.x = tf32r(v.x); v.y = tf32r(v.y); v.z = tf32r(v.z); v.w = tf32r(v.w);
            *(float4*)&As[r][ac4] = v;
        }
        // ---- load B tile ----
#pragma unroll
        for (int i = 0; i < 4; i++) {
            int r = br0 + i * 8;
            float4 v = *(const float4*)(W + (size_t)(kt + r) * N + bn * 128 + bc4);
            v.x = tf32r(v.x); v.y = tf32r(v.y); v.z = tf32r(v.z); v.w = tf32r(v.w);
            *(float4*)&Bs[r][bc4] = v;
        }
        __syncthreads();

#pragma unroll
        for (int kk = 0; kk < 32; kk += 8) {
            uint32_t af[2][4], bf[8][2];
#pragma unroll
            for (int mt = 0; mt < 2; mt++) {
                int ar = warp_m * 32 + mt * 16 + grp;
                int ac = kk + tig;
                af[mt][0] = __float_as_uint(As[ar][ac]);
                af[mt][1] = __float_as_uint(As[ar + 8][ac]);
                af[mt][2] = __float_as_uint(As[ar][ac + 4]);
                af[mt][3] = __float_as_uint(As[ar + 8][ac + 4]);
            }
#pragma unroll
            for (int nt = 0; nt < 8; nt++) {
                int bc = warp_n * 64 + nt * 8 + grp;
                bf[nt][0] = __float_as_uint(Bs[kk + tig][bc]);
                bf[nt][1] = __float_as_uint(Bs[kk + tig + 4][bc]);
            }
#pragma unroll
            for (int mt = 0; mt < 2; mt++)
#pragma unroll
                for (int nt = 0; nt < 8; nt++)
                    mma8(acc[mt][nt], af[mt], bf[nt]);
        }
        __syncthreads();
    }

    // ---- epilogue ----
#pragma unroll
    for (int mt = 0; mt < 2; mt++) {
#pragma unroll
        for (int nt = 0; nt < 8; nt++) {
            int r0 = bm * 128 + warp_m * 32 + mt * 16 + grp;
            int c0 = bn * 128 + warp_n * 64 + nt * 8 + 2 * tig;
#pragma unroll
            for (int half = 0; half < 2; half++) {
                int r = r0 + half * 8;
                float v0 = acc[mt][nt][half * 2 + 0];
                float v1 = acc[mt][nt][half * 2 + 1];
                float2 bs = *(const float2*)(bias + c0);
                v0 += bs.x; v1 += bs.y;
                size_t idx = (size_t)r * N + c0;
                float2 o;
                if (EPI == 0) {
                    o.x = silu(v0); o.y = silu(v1);
                } else if (EPI == 1) {
                    float2 cv = *(const float2*)(conv + idx);
                    float2 xr = *(const float2*)(xres + idx);
                    o.x = cv.x * silu(v0) + xr.x;
                    o.y = cv.y * silu(v1) + xr.y;
                } else {
                    float2 xr = *(const float2*)(xres + idx);
                    o.x = v0 + xr.x;
                    o.y = v1 + xr.y;
                }
                *(float2*)(out + idx) = o;
            }
        }
    }
}

__global__ void __launch_bounds__(256) k_gemm1(const float* __restrict__ x,
                                               const float* __restrict__ w,
                                               const float* __restrict__ b) {
    gemm_body<1, false>(x, w, b, DD, DD, nullptr, nullptr, nullptr, g_conv, x, g_x2);
}
__global__ void __launch_bounds__(256) k_gemm2(const float* __restrict__ w,
                                               const float* __restrict__ b,
                                               const float* __restrict__ lng,
                                               const float* __restrict__ lnb) {
    gemm_body<0, true>(g_x2, w, b, FFD, DD, g_st2, lng, lnb, nullptr, nullptr, g_hid);
}
__global__ void __launch_bounds__(256) k_gemm3(const float* __restrict__ w,
                                               const float* __restrict__ b,
                                               float* __restrict__ out) {
    gemm_body<2, false>(g_hid, w, b, DD, FFD, nullptr, nullptr, nullptr, nullptr, g_x2, out);
}

// ---------------- launch -----------------------------------------------------
extern "C" void kernel_launch(void* const* d_in, const int* in_sizes, int n_in,
                              void* d_out, int out_size) {
    const float* x     = (const float*)d_in[0];
    const float* ln_g  = (const float*)d_in[1];
    const float* ln_b  = (const float*)d_in[2];
    const float* fc_w  = (const float*)d_in[3];
    const float* fc_b  = (const float*)d_in[4];
    const float* w1    = (const float*)d_in[5];
    const float* b1    = (const float*)d_in[6];
    const float* w2    = (const float*)d_in[7];
    const float* b2    = (const float*)d_in[8];
    const float* ph_re = (const float*)d_in[9];
    const float* ph_im = (const float*)d_in[10];
    const float* phi_re= (const float*)d_in[11];
    const float* phi_im= (const float*)d_in[12];
    const float* lci_re= (const float*)d_in[13];
    const float* lci_im= (const float*)d_in[14];
    float* out = (float*)d_out;

    // 1) LN stats of x
    k_stats1<<<MROWS, 256>>>(x);
    // 2-4) spiral conv scan
    k_scan<false><<<dim3(CC, BB), 1024>>>(x, ph_re, ph_im, phi_re, phi_im, ln_g, ln_b);
    k_scan2<<<(BB * DD) / 256, 256>>>(ph_re, ph_im, lci_re, lci_im);
    k_scan<true><<<dim3(CC, BB), 1024>>>(x, ph_re, ph_im, phi_re, phi_im, ln_g, ln_b);
    // 5) x2 = conv * silu(x@fc_w+fc_b) + x
    k_gemm1<<<dim3(DD / 128, MROWS / 128), 256>>>(x, fc_w, fc_b);
    // 6) LN stats of x2
    k_stats2<<<MROWS, 256>>>();
    // 7) hid = silu(LN(x2)@w1 + b1)
    k_gemm2<<<dim3(FFD / 128, MROWS / 128), 256>>>(w1, b1, ln_g, ln_b);
    // 8) out = x2 + hid@w2 + b2
    k_gemm3<<<dim3(DD / 128, MROWS / 128), 256>>>(w2, b2, out);
}

// round 3
// speedup vs baseline: 1.0744x; 1.0744x over previous
#include <cuda_runtime.h>
#include <cuda_bf16.h>
#include <cstdint>

// Problem constants
constexpr int BB = 4;
constexpr int LL = 4096;
constexpr int DD = 1024;
constexpr int FFD = 2048;
constexpr int TT = 32;              // scan chunk length
constexpr int CC = LL / TT;         // 128 chunks
constexpr int MROWS = BB * LL;      // 16384
constexpr float EPS = 1e-5f;

// ---------------- scratch (device globals; no runtime allocation) ----------
__device__ float  g_conv[BB * LL * DD];
__device__ float  g_x2  [BB * LL * DD];
__device__ float  g_x3  [BB * LL * DD];
__device__ float  g_hid [(size_t)BB * LL * FFD];
__device__ float2 g_st1 [BB * LL];
__device__ float2 g_cv  [BB * CC * DD];
__device__ float2 g_carry[BB * CC * DD];

// ---------------- helpers ---------------------------------------------------
__device__ __forceinline__ float silu(float v) {
    return v / (1.0f + expf(-v));
}

__device__ __forceinline__ void mma8(float* c, const uint32_t* a, const uint32_t* b) {
    asm volatile(
        "mma.sync.aligned.m16n8k8.row.col.f32.tf32.tf32.f32 "
        "{%0,%1,%2,%3}, {%4,%5,%6,%7}, {%8,%9}, {%0,%1,%2,%3};\n"
        : "+f"(c[0]), "+f"(c[1]), "+f"(c[2]), "+f"(c[3])
        : "r"(a[0]), "r"(a[1]), "r"(a[2]), "r"(a[3]), "r"(b[0]), "r"(b[1]));
}

#define CP_ASYNC16(dst_u32, src_ptr) \
    asm volatile("cp.async.cg.shared.global [%0], [%1], 16;\n" :: "r"(dst_u32), "l"(src_ptr))
#define CP_COMMIT() asm volatile("cp.async.commit_group;\n" ::)
#define CP_WAIT(n)  asm volatile("cp.async.wait_group %0;\n" :: "n"(n))

// ---------------- LayerNorm row stats (for x, consumed by the scan) ---------
__global__ void k_stats1(const float* __restrict__ x) {
    int row = blockIdx.x;
    int tid = threadIdx.x;          // 256 threads, 4 floats each = 1024
    float4 v = *(const float4*)(x + (size_t)row * DD + tid * 4);
    float s = v.x + v.y + v.z + v.w;
    float q = v.x * v.x + v.y * v.y + v.z * v.z + v.w * v.w;
#pragma unroll
    for (int o = 16; o; o >>= 1) {
        s += __shfl_xor_sync(0xffffffffu, s, o);
        q += __shfl_xor_sync(0xffffffffu, q, o);
    }
    __shared__ float2 ws[8];
    if ((tid & 31) == 0) ws[tid >> 5] = make_float2(s, q);
    __syncthreads();
    if (tid < 8) {
        float ss = ws[tid].x, qq = ws[tid].y;
#pragma unroll
        for (int o = 4; o; o >>= 1) {
            ss += __shfl_xor_sync(0xffu, ss, o);
            qq += __shfl_xor_sync(0xffu, qq, o);
        }
        if (tid == 0) {
            float mean = ss * (1.0f / DD);
            float var  = qq * (1.0f / DD) - mean * mean;
            g_st1[row] = make_float2(mean, rsqrtf(var + EPS));
        }
    }
}

// ---------------- fused LN: x3 = LayerNorm(x2) -------------------------------
__global__ void k_lnx(const float* __restrict__ lng, const float* __restrict__ lnb) {
    int row = blockIdx.x;
    int tid = threadIdx.x;          // 256 threads x float4
    float4 v = *(const float4*)(g_x2 + (size_t)row * DD + tid * 4);
    float s = v.x + v.y + v.z + v.w;
    float q = v.x * v.x + v.y * v.y + v.z * v.z + v.w * v.w;
#pragma unroll
    for (int o = 16; o; o >>= 1) {
        s += __shfl_xor_sync(0xffffffffu, s, o);
        q += __shfl_xor_sync(0xffffffffu, q, o);
    }
    __shared__ float2 ws[8];
    __shared__ float2 fin;
    if ((tid & 31) == 0) ws[tid >> 5] = make_float2(s, q);
    __syncthreads();
    if (tid == 0) {
        float ss = 0.0f, qq = 0.0f;
#pragma unroll
        for (int i = 0; i < 8; i++) { ss += ws[i].x; qq += ws[i].y; }
        float mean = ss * (1.0f / DD);
        float var  = qq * (1.0f / DD) - mean * mean;
        fin = make_float2(mean, rsqrtf(var + EPS));
    }
    __syncthreads();
    float mean = fin.x, rstd = fin.y;
    float4 gg = *(const float4*)(lng + tid * 4);
    float4 bb = *(const float4*)(lnb + tid * 4);
    float4 o;
    o.x = (v.x - mean) * rstd * gg.x + bb.x;
    o.y = (v.y - mean) * rstd * gg.y + bb.y;
    o.z = (v.z - mean) * rstd * gg.z + bb.z;
    o.w = (v.w - mean) * rstd * gg.w + bb.w;
    *(float4*)(g_x3 + (size_t)row * DD + tid * 4) = o;
}

// ---------------- spiral-conv scan ------------------------------------------
// c[t] = phz*c[t-1] + phi*xn[t],  c[-1] = lci,  phz = ph/|ph| * exp(-|ph|)

template <bool PHASE3>
__global__ void __launch_bounds__(1024) k_scan(
    const float* __restrict__ x,
    const float* __restrict__ phre, const float* __restrict__ phim,
    const float* __restrict__ phir, const float* __restrict__ phii,
    const float* __restrict__ lng,  const float* __restrict__ lnb) {
    int d = threadIdx.x;
    int j = blockIdx.x;   // chunk
    int b = blockIdx.y;   // batch

    float pre = phre[d], pim = phim[d];
    float a  = sqrtf(pre * pre + pim * pim);
    float sc = expf(-a) / a;
    float pzr = pre * sc, pzi = pim * sc;
    float fr = phir[d], fi = phii[d];
    float g = lng[d], bbv = lnb[d];

    size_t rowbase = (size_t)b * LL + (size_t)j * TT;
    float cr, ci;
    if (PHASE3) {
        float2 cc = g_carry[((size_t)b * CC + j) * DD + d];
        cr = cc.x; ci = cc.y;
    } else {
        cr = 0.0f; ci = 0.0f;
    }
    const float* xp = x + rowbase * DD + d;
#pragma unroll 4
    for (int s = 0; s < TT; s++) {
        float2 st = g_st1[rowbase + s];
        float xv = xp[(size_t)s * DD];
        float xn = (xv - st.x) * st.y * g + bbv;
        float nr = cr * pzr - ci * pzi + fr * xn;
        float ni = cr * pzi + ci * pzr + fi * xn;
        cr = nr; ci = ni;
        if (PHASE3) g_conv[rowbase * DD + (size_t)s * DD + d] = cr;
    }
    if (!PHASE3) g_cv[((size_t)b * CC + j) * DD + d] = make_float2(cr, ci);
}

__global__ void k_scan2(const float* __restrict__ phre, const float* __restrict__ phim,
                        const float* __restrict__ lcire, const float* __restrict__ lciim) {
    int idx = blockIdx.x * blockDim.x + threadIdx.x;   // BB*DD threads
    int b = idx / DD, d = idx % DD;
    float pre = phre[d], pim = phim[d];
    float a  = sqrtf(pre * pre + pim * pim);
    float sc = expf(-a) / a;
    float tr = pre * sc, ti = pim * sc;
    // phz^TT, TT = 32 = 2^5 -> 5 complex squarings
#pragma unroll
    for (int i = 0; i < 5; i++) {
        float nr = tr * tr - ti * ti;
        ti = 2.0f * tr * ti;
        tr = nr;
    }
    float cr = lcire[d], ci = lciim[d];
    const float2* cv = g_cv + (size_t)b * CC * DD + d;
    float2* carry    = g_carry + (size_t)b * CC * DD + d;
    carry[0] = make_float2(cr, ci);
    int jj = 0;
    // batch loads 4-deep (independent of the recurrence) for MLP
    for (; jj + 4 <= CC - 1; jj += 4) {
        float2 v0 = cv[(size_t)(jj + 0) * DD];
        float2 v1 = cv[(size_t)(jj + 1) * DD];
        float2 v2 = cv[(size_t)(jj + 2) * DD];
        float2 v3 = cv[(size_t)(jj + 3) * DD];
        float nr, ni;
        nr = tr * cr - ti * ci + v0.x; ni = tr * ci + ti * cr + v0.y; cr = nr; ci = ni;
        carry[(size_t)(jj + 1) * DD] = make_float2(cr, ci);
        nr = tr * cr - ti * ci + v1.x; ni = tr * ci + ti * cr + v1.y; cr = nr; ci = ni;
        carry[(size_t)(jj + 2) * DD] = make_float2(cr, ci);
        nr = tr * cr - ti * ci + v2.x; ni = tr * ci + ti * cr + v2.y; cr = nr; ci = ni;
        carry[(size_t)(jj + 3) * DD] = make_float2(cr, ci);
        nr = tr * cr - ti * ci + v3.x; ni = tr * ci + ti * cr + v3.y; cr = nr; ci = ni;
        carry[(size_t)(jj + 4) * DD] = make_float2(cr, ci);
    }
    for (; jj < CC - 1; jj++) {
        float2 v = cv[(size_t)jj * DD];
        float nr = tr * cr - ti * ci + v.x;
        float ni = tr * ci + ti * cr + v.y;
        cr = nr; ci = ni;
        carry[(size_t)(jj + 1) * DD] = make_float2(cr, ci);
    }
}

// ---------------- tf32 tensor-core GEMM, cp.async 2-stage pipeline -----------
// C = A[M,K] @ W[K,N]; BM=BN=128, BK=16; 256 threads, 8 warps of 32x64.
// Static shared memory (37.9KB) -> no cudaFuncSetAttribute needed.
// EPI 0: out = silu(acc+bias)                   (gemm2 -> hid)
// EPI 1: out = conv * silu(acc+bias) + xres     (gemm1 -> x2)
// EPI 2: out = acc + bias + xres                (gemm3 -> final)

constexpr int BK = 16;
constexpr int AS_STRIDE = 20;    // floats per A row (16 + 4 pad, 16B-aligned)
constexpr int BS_STRIDE = 136;   // floats per B row (128 + 8 pad, 16B-aligned)
constexpr int AS_STAGE  = 128 * AS_STRIDE;   // 2560 floats
constexpr int BS_STAGE  = BK * BS_STRIDE;    // 2176 floats

template <int EPI>
__device__ __forceinline__ void gemm_body(
    const float* __restrict__ A, const float* __restrict__ W,
    const float* __restrict__ bias, int N, int K,
    const float* __restrict__ conv, const float* __restrict__ xres,
    float* __restrict__ out) {
    __shared__ float Asm[2 * AS_STAGE];
    __shared__ float Bsm[2 * BS_STAGE];
    uint32_t Asm_u = (uint32_t)__cvta_generic_to_shared(Asm);
    uint32_t Bsm_u = (uint32_t)__cvta_generic_to_shared(Bsm);

    int tid = threadIdx.x;
    int lane = tid & 31, wid = tid >> 5;
    int warp_m = wid >> 1;      // 0..3  (32-row slabs)
    int warp_n = wid & 1;       // 0..1  (64-col slabs)
    int grp = lane >> 2, tig = lane & 3;
    int bm = blockIdx.y, bn = blockIdx.x;

    float acc[2][8][4];
#pragma unroll
    for (int mt = 0; mt < 2; mt++)
#pragma unroll
        for (int nt = 0; nt < 8; nt++)
#pragma unroll
            for (int i = 0; i < 4; i++) acc[mt][nt][i] = 0.0f;

    int ar0 = tid >> 2, ac4 = (tid & 3) * 4;       // A loader: 64 rows/pass, 2 passes
    int br0 = tid >> 5, bc4 = (tid & 31) * 4;      // B loader: 8 rows/pass,  2 passes

    const int ntiles = K / BK;

    // tile loader into stage s
    auto load_tile = [&](int kt, int s) {
#pragma unroll
        for (int i = 0; i < 2; i++) {
            int r = ar0 + i * 64;
            uint32_t dst = Asm_u + (uint32_t)((s * AS_STAGE + r * AS_STRIDE + ac4) * 4);
            CP_ASYNC16(dst, A + (size_t)(bm * 128 + r) * K + kt + ac4);
        }
#pragma unroll
        for (int i = 0; i < 2; i++) {
            int r = br0 + i * 8;
            uint32_t dst = Bsm_u + (uint32_t)((s * BS_STAGE + r * BS_STRIDE + bc4) * 4);
            CP_ASYNC16(dst, W + (size_t)(kt + r) * N + bn * 128 + bc4);
        }
        CP_COMMIT();
    };

    load_tile(0, 0);

    for (int t = 0; t < ntiles; t++) {
        int s = t & 1;
        if (t + 1 < ntiles) {
            load_tile((t + 1) * BK, s ^ 1);
            CP_WAIT(1);
        } else {
            CP_WAIT(0);
        }
        __syncthreads();

        const float* As = Asm + s * AS_STAGE;
        const float* Bs = Bsm + s * BS_STAGE;
#pragma unroll
        for (int kk = 0; kk < BK; kk += 8) {
            uint32_t af[2][4], bf[8][2];
#pragma unroll
            for (int mt = 0; mt < 2; mt++) {
                int ar = warp_m * 32 + mt * 16 + grp;
                int ac = kk + tig;
                af[mt][0] = __float_as_uint(As[ar * AS_STRIDE + ac]);
                af[mt][1] = __float_as_uint(As[(ar + 8) * AS_STRIDE + ac]);
                af[mt][2] = __float_as_uint(As[ar * AS_STRIDE + ac + 4]);
                af[mt][3] = __float_as_uint(As[(ar + 8) * AS_STRIDE + ac + 4]);
            }
#pragma unroll
            for (int nt = 0; nt < 8; nt++) {
                int bc = warp_n * 64 + nt * 8 + grp;
                bf[nt][0] = __float_as_uint(Bs[(kk + tig) * BS_STRIDE + bc]);
                bf[nt][1] = __float_as_uint(Bs[(kk + tig + 4) * BS_STRIDE + bc]);
            }
#pragma unroll
            for (int mt = 0; mt < 2; mt++)
#pragma unroll
                for (int nt = 0; nt < 8; nt++)
                    mma8(acc[mt][nt], af[mt], bf[nt]);
        }
        __syncthreads();
    }

    // ---- epilogue ----
#pragma unroll
    for (int mt = 0; mt < 2; mt++) {
#pragma unroll
        for (int nt = 0; nt < 8; nt++) {
            int r0 = bm * 128 + warp_m * 32 + mt * 16 + grp;
            int c0 = bn * 128 + warp_n * 64 + nt * 8 + 2 * tig;
#pragma unroll
            for (int half = 0; half < 2; half++) {
                int r = r0 + half * 8;
                float v0 = acc[mt][nt][half * 2 + 0];
                float v1 = acc[mt][nt][half * 2 + 1];
                float2 bs = *(const float2*)(bias + c0);
                v0 += bs.x; v1 += bs.y;
                size_t idx = (size_t)r * N + c0;
                float2 o;
                if (EPI == 0) {
                    o.x = silu(v0); o.y = silu(v1);
                } else if (EPI == 1) {
                    float2 cv = *(const float2*)(conv + idx);
                    float2 xr = *(const float2*)(xres + idx);
                    o.x = cv.x * silu(v0) + xr.x;
                    o.y = cv.y * silu(v1) + xr.y;
                } else {
                    float2 xr = *(const float2*)(xres + idx);
                    o.x = v0 + xr.x;
                    o.y = v1 + xr.y;
                }
                *(float2*)(out + idx) = o;
            }
        }
    }
}

__global__ void __launch_bounds__(256) k_gemm1(const float* __restrict__ x,
                                               const float* __restrict__ w,
                                               const float* __restrict__ b) {
    gemm_body<1>(x, w, b, DD, DD, g_conv, x, g_x2);
}
__global__ void __launch_bounds__(256) k_gemm2(const float* __restrict__ w,
                                               const float* __restrict__ b) {
    gemm_body<0>(g_x3, w, b, FFD, DD, nullptr, nullptr, g_hid);
}
__global__ void __launch_bounds__(256) k_gemm3(const float* __restrict__ w,
                                               const float* __restrict__ b,
                                               float* __restrict__ out) {
    gemm_body<2>(g_hid, w, b, DD, FFD, nullptr, g_x2, out);
}

// ---------------- launch -----------------------------------------------------
extern "C" void kernel_launch(void* const* d_in, const int* in_sizes, int n_in,
                              void* d_out, int out_size) {
    const float* x     = (const float*)d_in[0];
    const float* ln_g  = (const float*)d_in[1];
    const float* ln_b  = (const float*)d_in[2];
    const float* fc_w  = (const float*)d_in[3];
    const float* fc_b  = (const float*)d_in[4];
    const float* w1    = (const float*)d_in[5];
    const float* b1    = (const float*)d_in[6];
    const float* w2    = (const float*)d_in[7];
    const float* b2    = (const float*)d_in[8];
    const float* ph_re = (const float*)d_in[9];
    const float* ph_im = (const float*)d_in[10];
    const float* phi_re= (const float*)d_in[11];
    const float* phi_im= (const float*)d_in[12];
    const float* lci_re= (const float*)d_in[13];
    const float* lci_im= (const float*)d_in[14];
    float* out = (float*)d_out;

    // 1) LN stats of x
    k_stats1<<<MROWS, 256>>>(x);
    // 2-4) spiral conv scan
    k_scan<false><<<dim3(CC, BB), 1024>>>(x, ph_re, ph_im, phi_re, phi_im, ln_g, ln_b);
    k_scan2<<<(BB * DD) / 256, 256>>>(ph_re, ph_im, lci_re, lci_im);
    k_scan<true><<<dim3(CC, BB), 1024>>>(x, ph_re, ph_im, phi_re, phi_im, ln_g, ln_b);
    // 5) x2 = conv * silu(x@fc_w+fc_b) + x
    k_gemm1<<<dim3(DD / 128, MROWS / 128), 256>>>(x, fc_w, fc_b);
    // 6) x3 = LN(x2)
    k_lnx<<<MROWS, 256>>>(ln_g, ln_b);
    // 7) hid = silu(x3@w1 + b1)
    k_gemm2<<<dim3(FFD / 128, MROWS / 128), 256>>>(w1, b1);
    // 8) out = x2 + hid@w2 + b2
    k_gemm3<<<dim3(DD / 128, MROWS / 128), 256>>>(w2, b2, out);
}

// round 5
// speedup vs baseline: 1.1155x; 1.0382x over previous
#include <cuda_runtime.h>
#include <cstdint>

// Problem constants
constexpr int BB = 4;
constexpr int LL = 4096;
constexpr int DD = 1024;
constexpr int FFD = 2048;
constexpr int TT = 32;              // scan chunk length
constexpr int CC = LL / TT;         // 128 chunks
constexpr int MROWS = BB * LL;      // 16384
constexpr float EPS = 1e-5f;

// ---------------- scratch (device globals; no runtime allocation) ----------
__device__ float  g_conv[BB * LL * DD];
__device__ float  g_x2  [BB * LL * DD];
__device__ float  g_x3  [BB * LL * DD];
__device__ float  g_xr  [BB * LL * DD];
__device__ float  g_hid [(size_t)BB * LL * FFD];
__device__ float  g_fcwr[DD * DD];
__device__ float  g_w1r [DD * FFD];
__device__ float  g_w2r [FFD * DD];
__device__ float2 g_st1 [BB * LL];
__device__ float2 g_cv  [BB * CC * DD];
__device__ float2 g_carry[BB * CC * DD];

// ---------------- helpers ---------------------------------------------------
__device__ __forceinline__ float tf32r(float x) {
    uint32_t u;
    asm("cvt.rna.tf32.f32 %0, %1;" : "=r"(u) : "f"(x));
    return __uint_as_float(u);
}
__device__ __forceinline__ float silu(float v) {
    return v / (1.0f + expf(-v));
}

__device__ __forceinline__ void mma8(float* c, const uint32_t* a, const uint32_t* b) {
    asm volatile(
        "mma.sync.aligned.m16n8k8.row.col.f32.tf32.tf32.f32 "
        "{%0,%1,%2,%3}, {%4,%5,%6,%7}, {%8,%9}, {%0,%1,%2,%3};\n"
        : "+f"(c[0]), "+f"(c[1]), "+f"(c[2]), "+f"(c[3])
        : "r"(a[0]), "r"(a[1]), "r"(a[2]), "r"(a[3]), "r"(b[0]), "r"(b[1]));
}

#define CP_ASYNC16(dst_u32, src_ptr) \
    asm volatile("cp.async.cg.shared.global [%0], [%1], 16;\n" :: "r"(dst_u32), "l"(src_ptr))
#define CP_COMMIT() asm volatile("cp.async.commit_group;\n" ::)
#define CP_WAIT(n)  asm volatile("cp.async.wait_group %0;\n" :: "n"(n))

// ---------------- weight rounding (rna -> tf32) ------------------------------
__global__ void k_round(const float* __restrict__ src, float* __restrict__ dst) {
    int i = blockIdx.x * blockDim.x + threadIdx.x;
    float4 v = ((const float4*)src)[i];
    v.x = tf32r(v.x); v.y = tf32r(v.y); v.z = tf32r(v.z); v.w = tf32r(v.w);
    ((float4*)dst)[i] = v;
}

// ---------------- LayerNorm row stats of x (+ rounded copy for GEMM A) -------
__global__ void k_stats1(const float* __restrict__ x) {
    int row = blockIdx.x;
    int tid = threadIdx.x;          // 256 threads, 4 floats each = 1024
    float4 v = *(const float4*)(x + (size_t)row * DD + tid * 4);
    float4 rv;
    rv.x = tf32r(v.x); rv.y = tf32r(v.y); rv.z = tf32r(v.z); rv.w = tf32r(v.w);
    *(float4*)(g_xr + (size_t)row * DD + tid * 4) = rv;
    float s = v.x + v.y + v.z + v.w;
    float q = v.x * v.x + v.y * v.y + v.z * v.z + v.w * v.w;
#pragma unroll
    for (int o = 16; o; o >>= 1) {
        s += __shfl_xor_sync(0xffffffffu, s, o);
        q += __shfl_xor_sync(0xffffffffu, q, o);
    }
    __shared__ float2 ws[8];
    if ((tid & 31) == 0) ws[tid >> 5] = make_float2(s, q);
    __syncthreads();
    if (tid < 8) {
        float ss = ws[tid].x, qq = ws[tid].y;
#pragma unroll
        for (int o = 4; o; o >>= 1) {
            ss += __shfl_xor_sync(0xffu, ss, o);
            qq += __shfl_xor_sync(0xffu, qq, o);
        }
        if (tid == 0) {
            float mean = ss * (1.0f / DD);
            float var  = qq * (1.0f / DD) - mean * mean;
            g_st1[row] = make_float2(mean, rsqrtf(var + EPS));
        }
    }
}

// ---------------- fused LN: x3 = round(LayerNorm(x2)) ------------------------
__global__ void k_lnx(const float* __restrict__ lng, const float* __restrict__ lnb) {
    int row = blockIdx.x;
    int tid = threadIdx.x;
    float4 v = *(const float4*)(g_x2 + (size_t)row * DD + tid * 4);
    float s = v.x + v.y + v.z + v.w;
    float q = v.x * v.x + v.y * v.y + v.z * v.z + v.w * v.w;
#pragma unroll
    for (int o = 16; o; o >>= 1) {
        s += __shfl_xor_sync(0xffffffffu, s, o);
        q += __shfl_xor_sync(0xffffffffu, q, o);
    }
    __shared__ float2 ws[8];
    __shared__ float2 fin;
    if ((tid & 31) == 0) ws[tid >> 5] = make_float2(s, q);
    __syncthreads();
    if (tid == 0) {
        float ss = 0.0f, qq = 0.0f;
#pragma unroll
        for (int i = 0; i < 8; i++) { ss += ws[i].x; qq += ws[i].y; }
        float mean = ss * (1.0f / DD);
        float var  = qq * (1.0f / DD) - mean * mean;
        fin = make_float2(mean, rsqrtf(var + EPS));
    }
    __syncthreads();
    float mean = fin.x, rstd = fin.y;
    float4 gg = *(const float4*)(lng + tid * 4);
    float4 bb = *(const float4*)(lnb + tid * 4);
    float4 o;
    o.x = tf32r((v.x - mean) * rstd * gg.x + bb.x);
    o.y = tf32r((v.y - mean) * rstd * gg.y + bb.y);
    o.z = tf32r((v.z - mean) * rstd * gg.z + bb.z);
    o.w = tf32r((v.w - mean) * rstd * gg.w + bb.w);
    *(float4*)(g_x3 + (size_t)row * DD + tid * 4) = o;
}

// ---------------- spiral-conv scan ------------------------------------------
// c[t] = phz*c[t-1] + phi*xn[t],  c[-1] = lci,  phz = ph/|ph| * exp(-|ph|)

template <bool PHASE3>
__global__ void __launch_bounds__(1024) k_scan(
    const float* __restrict__ x,
    const float* __restrict__ phre, const float* __restrict__ phim,
    const float* __restrict__ phir, const float* __restrict__ phii,
    const float* __restrict__ lng,  const float* __restrict__ lnb) {
    int d = threadIdx.x;
    int j = blockIdx.x;
    int b = blockIdx.y;

    float pre = phre[d], pim = phim[d];
    float a  = sqrtf(pre * pre + pim * pim);
    float sc = expf(-a) / a;
    float pzr = pre * sc, pzi = pim * sc;
    float fr = phir[d], fi = phii[d];
    float g = lng[d], bbv = lnb[d];

    size_t rowbase = (size_t)b * LL + (size_t)j * TT;
    float cr, ci;
    if (PHASE3) {
        float2 cc = g_carry[((size_t)b * CC + j) * DD + d];
        cr = cc.x; ci = cc.y;
    } else {
        cr = 0.0f; ci = 0.0f;
    }
    const float* xp = x + rowbase * DD + d;
#pragma unroll 4
    for (int s = 0; s < TT; s++) {
        float2 st = g_st1[rowbase + s];
        float xv = xp[(size_t)s * DD];
        float xn = (xv - st.x) * st.y * g + bbv;
        float nr = cr * pzr - ci * pzi + fr * xn;
        float ni = cr * pzi + ci * pzr + fi * xn;
        cr = nr; ci = ni;
        if (PHASE3) g_conv[rowbase * DD + (size_t)s * DD + d] = cr;
    }
    if (!PHASE3) g_cv[((size_t)b * CC + j) * DD + d] = make_float2(cr, ci);
}

__global__ void k_scan2(const float* __restrict__ phre, const float* __restrict__ phim,
                        const float* __restrict__ lcire, const float* __restrict__ lciim) {
    int idx = blockIdx.x * blockDim.x + threadIdx.x;
    int b = idx / DD, d = idx % DD;
    float pre = phre[d], pim = phim[d];
    float a  = sqrtf(pre * pre + pim * pim);
    float sc = expf(-a) / a;
    float tr = pre * sc, ti = pim * sc;
#pragma unroll
    for (int i = 0; i < 5; i++) {
        float nr = tr * tr - ti * ti;
        ti = 2.0f * tr * ti;
        tr = nr;
    }
    float cr = lcire[d], ci = lciim[d];
    const float2* cv = g_cv + (size_t)b * CC * DD + d;
    float2* carry    = g_carry + (size_t)b * CC * DD + d;
    carry[0] = make_float2(cr, ci);
    int jj = 0;
    for (; jj + 4 <= CC - 1; jj += 4) {
        float2 v0 = cv[(size_t)(jj + 0) * DD];
        float2 v1 = cv[(size_t)(jj + 1) * DD];
        float2 v2 = cv[(size_t)(jj + 2) * DD];
        float2 v3 = cv[(size_t)(jj + 3) * DD];
        float nr, ni;
        nr = tr * cr - ti * ci + v0.x; ni = tr * ci + ti * cr + v0.y; cr = nr; ci = ni;
        carry[(size_t)(jj + 1) * DD] = make_float2(cr, ci);
        nr = tr * cr - ti * ci + v1.x; ni = tr * ci + ti * cr + v1.y; cr = nr; ci = ni;
        carry[(size_t)(jj + 2) * DD] = make_float2(cr, ci);
        nr = tr * cr - ti * ci + v2.x; ni = tr * ci + ti * cr + v2.y; cr = nr; ci = ni;
        carry[(size_t)(jj + 3) * DD] = make_float2(cr, ci);
        nr = tr * cr - ti * ci + v3.x; ni = tr * ci + ti * cr + v3.y; cr = nr; ci = ni;
        carry[(size_t)(jj + 4) * DD] = make_float2(cr, ci);
    }
    for (; jj < CC - 1; jj++) {
        float2 v = cv[(size_t)jj * DD];
        float nr = tr * cr - ti * ci + v.x;
        float ni = tr * ci + ti * cr + v.y;
        cr = nr; ci = ni;
        carry[(size_t)(jj + 1) * DD] = make_float2(cr, ci);
    }
}

// ---------------- tf32 tensor-core GEMM, warp tile 64x64 ---------------------
// C = A[M,K] @ W[K,N]; BM=BN=128, BK=16; 128 threads = 4 warps (2x2 warp grid),
// each warp computes 64x64 -> 1.0 LDS per mma (vs 1.5 before), 64 mma per sync.
// Static smem 37.9KB. 2-stage cp.async pipeline.
// EPI 0: out = rna(silu(acc+bias));  EPI 1: out = conv*silu(acc+bias)+xres;
// EPI 2: out = acc+bias+xres.

constexpr int BK = 16;
constexpr int AS_STRIDE = 20;    // floats per A row (16 + 4 pad)
constexpr int BS_STRIDE = 136;   // floats per B row (128 + 8 pad)
constexpr int AS_STAGE  = 128 * AS_STRIDE;   // 2560 floats
constexpr int BS_STAGE  = BK * BS_STRIDE;    // 2176 floats

template <int EPI>
__device__ __forceinline__ void gemm_body(
    const float* __restrict__ A, const float* __restrict__ W,
    const float* __restrict__ bias, int N, int K,
    const float* __restrict__ conv, const float* __restrict__ xres,
    float* __restrict__ out) {
    __shared__ float Asm[2 * AS_STAGE];
    __shared__ float Bsm[2 * BS_STAGE];
    uint32_t Asm_u = (uint32_t)__cvta_generic_to_shared(Asm);
    uint32_t Bsm_u = (uint32_t)__cvta_generic_to_shared(Bsm);

    int tid = threadIdx.x;
    int lane = tid & 31, wid = tid >> 5;
    int warp_m = wid >> 1;      // 0..1  (64-row slabs)
    int warp_n = wid & 1;       // 0..1  (64-col slabs)
    int grp = lane >> 2, tig = lane & 3;
    int bm = blockIdx.y, bn = blockIdx.x;

    float acc[4][8][4];
#pragma unroll
    for (int mt = 0; mt < 4; mt++)
#pragma unroll
        for (int nt = 0; nt < 8; nt++)
#pragma unroll
            for (int i = 0; i < 4; i++) acc[mt][nt][i] = 0.0f;

    int ar0 = tid >> 2, ac4 = (tid & 3) * 4;       // A loader: 32 rows/pass, 4 passes
    int br0 = tid >> 5, bc4 = (tid & 31) * 4;      // B loader: 4 rows/pass,  4 passes

    const int ntiles = K / BK;

    auto load_tile = [&](int kt, int s) {
#pragma unroll
        for (int i = 0; i < 4; i++) {
            int r = ar0 + i * 32;
            uint32_t dst = Asm_u + (uint32_t)((s * AS_STAGE + r * AS_STRIDE + ac4) * 4);
            CP_ASYNC16(dst, A + (size_t)(bm * 128 + r) * K + kt + ac4);
        }
#pragma unroll
        for (int i = 0; i < 4; i++) {
            int r = br0 + i * 4;
            uint32_t dst = Bsm_u + (uint32_t)((s * BS_STAGE + r * BS_STRIDE + bc4) * 4);
            CP_ASYNC16(dst, W + (size_t)(kt + r) * N + bn * 128 + bc4);
        }
        CP_COMMIT();
    };

    load_tile(0, 0);

    for (int t = 0; t < ntiles; t++) {
        int s = t & 1;
        if (t + 1 < ntiles) {
            load_tile((t + 1) * BK, s ^ 1);
            CP_WAIT(1);
        } else {
            CP_WAIT(0);
        }
        __syncthreads();

        const float* As = Asm + s * AS_STAGE;
        const float* Bs = Bsm + s * BS_STAGE;
#pragma unroll
        for (int kk = 0; kk < BK; kk += 8) {
            uint32_t af[4][4], bf[8][2];
#pragma unroll
            for (int mt = 0; mt < 4; mt++) {
                int ar = warp_m * 64 + mt * 16 + grp;
                int ac = kk + tig;
                af[mt][0] = __float_as_uint(As[ar * AS_STRIDE + ac]);
                af[mt][1] = __float_as_uint(As[(ar + 8) * AS_STRIDE + ac]);
                af[mt][2] = __float_as_uint(As[ar * AS_STRIDE + ac + 4]);
                af[mt][3] = __float_as_uint(As[(ar + 8) * AS_STRIDE + ac + 4]);
            }
#pragma unroll
            for (int nt = 0; nt < 8; nt++) {
                int bc = warp_n * 64 + nt * 8 + grp;
                bf[nt][0] = __float_as_uint(Bs[(kk + tig) * BS_STRIDE + bc]);
                bf[nt][1] = __float_as_uint(Bs[(kk + tig + 4) * BS_STRIDE + bc]);
            }
#pragma unroll
            for (int mt = 0; mt < 4; mt++)
#pragma unroll
                for (int nt = 0; nt < 8; nt++)
                    mma8(acc[mt][nt], af[mt], bf[nt]);
        }
        __syncthreads();
    }

    // ---- epilogue ----
#pragma unroll
    for (int mt = 0; mt < 4; mt++) {
#pragma unroll
        for (int nt = 0; nt < 8; nt++) {
            int r0 = bm * 128 + warp_m * 64 + mt * 16 + grp;
            int c0 = bn * 128 + warp_n * 64 + nt * 8 + 2 * tig;
#pragma unroll
            for (int half = 0; half < 2; half++) {
                int r = r0 + half * 8;
                float v0 = acc[mt][nt][half * 2 + 0];
                float v1 = acc[mt][nt][half * 2 + 1];
                float2 bs = *(const float2*)(bias + c0);
                v0 += bs.x; v1 += bs.y;
                size_t idx = (size_t)r * N + c0;
                float2 o;
                if (EPI == 0) {
                    o.x = tf32r(silu(v0)); o.y = tf32r(silu(v1));
                } else if (EPI == 1) {
                    float2 cv = *(const float2*)(conv + idx);
                    float2 xr = *(const float2*)(xres + idx);
                    o.x = cv.x * silu(v0) + xr.x;
                    o.y = cv.y * silu(v1) + xr.y;
                } else {
                    float2 xr = *(const float2*)(xres + idx);
                    o.x = v0 + xr.x;
                    o.y = v1 + xr.y;
                }
                *(float2*)(out + idx) = o;
            }
        }
    }
}

__global__ void __launch_bounds__(128) k_gemm1(const float* __restrict__ x,
                                               const float* __restrict__ b) {
    gemm_body<1>(g_xr, g_fcwr, b, DD, DD, g_conv, x, g_x2);
}
__global__ void __launch_bounds__(128) k_gemm2(const float* __restrict__ b) {
    gemm_body<0>(g_x3, g_w1r, b, FFD, DD, nullptr, nullptr, g_hid);
}
__global__ void __launch_bounds__(128) k_gemm3(const float* __restrict__ b,
                                               float* __restrict__ out) {
    gemm_body<2>(g_hid, g_w2r, b, DD, FFD, nullptr, g_x2, out);
}

__global__ void k_roundw(const float* __restrict__ fcw, const float* __restrict__ w1,
                         const float* __restrict__ w2) {
    int i = blockIdx.x * blockDim.x + threadIdx.x;
    if (i < DD * DD / 4) {
        float4 v = ((const float4*)fcw)[i];
        v.x = tf32r(v.x); v.y = tf32r(v.y); v.z = tf32r(v.z); v.w = tf32r(v.w);
        ((float4*)g_fcwr)[i] = v;
    }
    if (i < DD * FFD / 4) {
        float4 v = ((const float4*)w1)[i];
        v.x = tf32r(v.x); v.y = tf32r(v.y); v.z = tf32r(v.z); v.w = tf32r(v.w);
        ((float4*)g_w1r)[i] = v;
        float4 u = ((const float4*)w2)[i];
        u.x = tf32r(u.x); u.y = tf32r(u.y); u.z = tf32r(u.z); u.w = tf32r(u.w);
        ((float4*)g_w2r)[i] = u;
    }
}

// ---------------- launch -----------------------------------------------------
extern "C" void kernel_launch(void* const* d_in, const int* in_sizes, int n_in,
                              void* d_out, int out_size) {
    const float* x     = (const float*)d_in[0];
    const float* ln_g  = (const float*)d_in[1];
    const float* ln_b  = (const float*)d_in[2];
    const float* fc_w  = (const float*)d_in[3];
    const float* fc_b  = (const float*)d_in[4];
    const float* w1    = (const float*)d_in[5];
    const float* b1    = (const float*)d_in[6];
    const float* w2    = (const float*)d_in[7];
    const float* b2    = (const float*)d_in[8];
    const float* ph_re = (const float*)d_in[9];
    const float* ph_im = (const float*)d_in[10];
    const float* phi_re= (const float*)d_in[11];
    const float* phi_im= (const float*)d_in[12];
    const float* lci_re= (const float*)d_in[13];
    const float* lci_im= (const float*)d_in[14];
    float* out = (float*)d_out;

    // 0) round weights to tf32 (rna); one kernel covers all three
    k_roundw<<<(DD * FFD / 4 + 255) / 256, 256>>>(fc_w, w1, w2);
    // 1) LN stats of x (+ rounded x copy)
    k_stats1<<<MROWS, 256>>>(x);
    // 2-4) spiral conv scan
    k_scan<false><<<dim3(CC, BB), 1024>>>(x, ph_re, ph_im, phi_re, phi_im, ln_g, ln_b);
    k_scan2<<<(BB * DD) / 256, 256>>>(ph_re, ph_im, lci_re, lci_im);
    k_scan<true><<<dim3(CC, BB), 1024>>>(x, ph_re, ph_im, phi_re, phi_im, ln_g, ln_b);
    // 5) x2 = conv * silu(x@fc_w+fc_b) + x
    k_gemm1<<<dim3(DD / 128, MROWS / 128), 128>>>(x, fc_b);
    // 6) x3 = round(LN(x2))
    k_lnx<<<MROWS, 256>>>(ln_g, ln_b);
    // 7) hid = round(silu(x3@w1 + b1))
    k_gemm2<<<dim3(FFD / 128, MROWS / 128), 128>>>(b1);
    // 8) out = x2 + hid@w2 + b2
    k_gemm3<<<dim3(DD / 128, MROWS / 128), 128>>>(b2, out);
}

// round 6
// speedup vs baseline: 1.8711x; 1.6774x over previous
#include <cuda_runtime.h>
#include <cuda_fp16.h>
#include <cstdint>

// Problem constants
constexpr int BB = 4;
constexpr int LL = 4096;
constexpr int DD = 1024;
constexpr int FFD = 2048;
constexpr int TT = 32;              // scan chunk length
constexpr int CC = LL / TT;         // 128 chunks
constexpr int MROWS = BB * LL;      // 16384
constexpr float EPS = 1e-5f;

// ---------------- scratch (device globals; no runtime allocation) ----------
__device__ float  g_conv[BB * LL * DD];
__device__ float  g_x2  [BB * LL * DD];
__device__ __half g_xh  [BB * LL * DD];
__device__ __half g_x3h [BB * LL * DD];
__device__ __half g_hidh[(size_t)BB * LL * FFD];
__device__ __half g_fcwh[DD * DD];
__device__ __half g_w1h [DD * FFD];
__device__ __half g_w2h [FFD * DD];
__device__ float2 g_st1 [BB * LL];
__device__ float2 g_cv  [BB * CC * DD];
__device__ float2 g_carry[BB * CC * DD];

// ---------------- helpers ---------------------------------------------------
__device__ __forceinline__ float silu(float v) {
    return v / (1.0f + expf(-v));
}

__device__ __forceinline__ void mma16(float* c, const uint32_t* a, const uint32_t* b) {
    asm volatile(
        "mma.sync.aligned.m16n8k16.row.col.f32.f16.f16.f32 "
        "{%0,%1,%2,%3}, {%4,%5,%6,%7}, {%8,%9}, {%0,%1,%2,%3};\n"
        : "+f"(c[0]), "+f"(c[1]), "+f"(c[2]), "+f"(c[3])
        : "r"(a[0]), "r"(a[1]), "r"(a[2]), "r"(a[3]), "r"(b[0]), "r"(b[1]));
}

#define LDMX4(r0, r1, r2, r3, addr) \
    asm volatile("ldmatrix.sync.aligned.m8n8.x4.shared.b16 {%0,%1,%2,%3}, [%4];" \
                 : "=r"(r0), "=r"(r1), "=r"(r2), "=r"(r3) : "r"(addr))
#define LDMX4T(r0, r1, r2, r3, addr) \
    asm volatile("ldmatrix.sync.aligned.m8n8.x4.trans.shared.b16 {%0,%1,%2,%3}, [%4];" \
                 : "=r"(r0), "=r"(r1), "=r"(r2), "=r"(r3) : "r"(addr))

#define CP_ASYNC16(dst_u32, src_ptr) \
    asm volatile("cp.async.cg.shared.global [%0], [%1], 16;\n" :: "r"(dst_u32), "l"(src_ptr))
#define CP_COMMIT() asm volatile("cp.async.commit_group;\n" ::)
#define CP_WAIT(n)  asm volatile("cp.async.wait_group %0;\n" :: "n"(n))

// ---------------- weight conversion fp32 -> fp16 (rn) ------------------------
__global__ void k_roundw(const float* __restrict__ fcw, const float* __restrict__ w1,
                         const float* __restrict__ w2) {
    int i = blockIdx.x * blockDim.x + threadIdx.x;   // float4 index
    if (i < DD * DD / 4) {
        float4 v = ((const float4*)fcw)[i];
        ((__half2*)g_fcwh)[2 * i]     = __floats2half2_rn(v.x, v.y);
        ((__half2*)g_fcwh)[2 * i + 1] = __floats2half2_rn(v.z, v.w);
    }
    if (i < DD * FFD / 4) {
        float4 v = ((const float4*)w1)[i];
        ((__half2*)g_w1h)[2 * i]     = __floats2half2_rn(v.x, v.y);
        ((__half2*)g_w1h)[2 * i + 1] = __floats2half2_rn(v.z, v.w);
        float4 u = ((const float4*)w2)[i];
        ((__half2*)g_w2h)[2 * i]     = __floats2half2_rn(u.x, u.y);
        ((__half2*)g_w2h)[2 * i + 1] = __floats2half2_rn(u.z, u.w);
    }
}

// ---------------- LN row stats of x (+ fp16 copy of x for GEMM1 A) -----------
__global__ void k_stats1(const float* __restrict__ x) {
    int row = blockIdx.x;
    int tid = threadIdx.x;          // 256 threads, 4 floats each = 1024
    float4 v = *(const float4*)(x + (size_t)row * DD + tid * 4);
    __half* hp = g_xh + (size_t)row * DD + tid * 4;
    *(__half2*)(hp)     = __floats2half2_rn(v.x, v.y);
    *(__half2*)(hp + 2) = __floats2half2_rn(v.z, v.w);
    float s = v.x + v.y + v.z + v.w;
    float q = v.x * v.x + v.y * v.y + v.z * v.z + v.w * v.w;
#pragma unroll
    for (int o = 16; o; o >>= 1) {
        s += __shfl_xor_sync(0xffffffffu, s, o);
        q += __shfl_xor_sync(0xffffffffu, q, o);
    }
    __shared__ float2 ws[8];
    if ((tid & 31) == 0) ws[tid >> 5] = make_float2(s, q);
    __syncthreads();
    if (tid < 8) {
        float ss = ws[tid].x, qq = ws[tid].y;
#pragma unroll
        for (int o = 4; o; o >>= 1) {
            ss += __shfl_xor_sync(0xffu, ss, o);
            qq += __shfl_xor_sync(0xffu, qq, o);
        }
        if (tid == 0) {
            float mean = ss * (1.0f / DD);
            float var  = qq * (1.0f / DD) - mean * mean;
            g_st1[row] = make_float2(mean, rsqrtf(var + EPS));
        }
    }
}

// ---------------- fused LN: x3h = fp16(LayerNorm(x2)) ------------------------
__global__ void k_lnx(const float* __restrict__ lng, const float* __restrict__ lnb) {
    int row = blockIdx.x;
    int tid = threadIdx.x;
    float4 v = *(const float4*)(g_x2 + (size_t)row * DD + tid * 4);
    float s = v.x + v.y + v.z + v.w;
    float q = v.x * v.x + v.y * v.y + v.z * v.z + v.w * v.w;
#pragma unroll
    for (int o = 16; o; o >>= 1) {
        s += __shfl_xor_sync(0xffffffffu, s, o);
        q += __shfl_xor_sync(0xffffffffu, q, o);
    }
    __shared__ float2 ws[8];
    __shared__ float2 fin;
    if ((tid & 31) == 0) ws[tid >> 5] = make_float2(s, q);
    __syncthreads();
    if (tid == 0) {
        float ss = 0.0f, qq = 0.0f;
#pragma unroll
        for (int i = 0; i < 8; i++) { ss += ws[i].x; qq += ws[i].y; }
        float mean = ss * (1.0f / DD);
        float var  = qq * (1.0f / DD) - mean * mean;
        fin = make_float2(mean, rsqrtf(var + EPS));
    }
    __syncthreads();
    float mean = fin.x, rstd = fin.y;
    float4 gg = *(const float4*)(lng + tid * 4);
    float4 bb = *(const float4*)(lnb + tid * 4);
    __half* hp = g_x3h + (size_t)row * DD + tid * 4;
    *(__half2*)(hp)     = __floats2half2_rn((v.x - mean) * rstd * gg.x + bb.x,
                                            (v.y - mean) * rstd * gg.y + bb.y);
    *(__half2*)(hp + 2) = __floats2half2_rn((v.z - mean) * rstd * gg.z + bb.z,
                                            (v.w - mean) * rstd * gg.w + bb.w);
}

// ---------------- spiral-conv scan ------------------------------------------
// c[t] = phz*c[t-1] + phi*xn[t],  c[-1] = lci,  phz = ph/|ph| * exp(-|ph|)

template <bool PHASE3>
__global__ void __launch_bounds__(1024) k_scan(
    const float* __restrict__ x,
    const float* __restrict__ phre, const float* __restrict__ phim,
    const float* __restrict__ phir, const float* __restrict__ phii,
    const float* __restrict__ lng,  const float* __restrict__ lnb) {
    int d = threadIdx.x;
    int j = blockIdx.x;
    int b = blockIdx.y;

    float pre = phre[d], pim = phim[d];
    float a  = sqrtf(pre * pre + pim * pim);
    float sc = expf(-a) / a;
    float pzr = pre * sc, pzi = pim * sc;
    float fr = phir[d], fi = phii[d];
    float g = lng[d], bbv = lnb[d];

    size_t rowbase = (size_t)b * LL + (size_t)j * TT;
    float cr, ci;
    if (PHASE3) {
        float2 cc = g_carry[((size_t)b * CC + j) * DD + d];
        cr = cc.x; ci = cc.y;
    } else {
        cr = 0.0f; ci = 0.0f;
    }
    const float* xp = x + rowbase * DD + d;
#pragma unroll 4
    for (int s = 0; s < TT; s++) {
        float2 st = g_st1[rowbase + s];
        float xv = xp[(size_t)s * DD];
        float xn = (xv - st.x) * st.y * g + bbv;
        float nr = cr * pzr - ci * pzi + fr * xn;
        float ni = cr * pzi + ci * pzr + fi * xn;
        cr = nr; ci = ni;
        if (PHASE3) g_conv[rowbase * DD + (size_t)s * DD + d] = cr;
    }
    if (!PHASE3) g_cv[((size_t)b * CC + j) * DD + d] = make_float2(cr, ci);
}

__global__ void k_scan2(const float* __restrict__ phre, const float* __restrict__ phim,
                        const float* __restrict__ lcire, const float* __restrict__ lciim) {
    int idx = blockIdx.x * blockDim.x + threadIdx.x;
    int b = idx / DD, d = idx % DD;
    float pre = phre[d], pim = phim[d];
    float a  = sqrtf(pre * pre + pim * pim);
    float sc = expf(-a) / a;
    float tr = pre * sc, ti = pim * sc;
#pragma unroll
    for (int i = 0; i < 5; i++) {
        float nr = tr * tr - ti * ti;
        ti = 2.0f * tr * ti;
        tr = nr;
    }
    float cr = lcire[d], ci = lciim[d];
    const float2* cv = g_cv + (size_t)b * CC * DD + d;
    float2* carry    = g_carry + (size_t)b * CC * DD + d;
    carry[0] = make_float2(cr, ci);
    int jj = 0;
    for (; jj + 4 <= CC - 1; jj += 4) {
        float2 v0 = cv[(size_t)(jj + 0) * DD];
        float2 v1 = cv[(size_t)(jj + 1) * DD];
        float2 v2 = cv[(size_t)(jj + 2) * DD];
        float2 v3 = cv[(size_t)(jj + 3) * DD];
        float nr, ni;
        nr = tr * cr - ti * ci + v0.x; ni = tr * ci + ti * cr + v0.y; cr = nr; ci = ni;
        carry[(size_t)(jj + 1) * DD] = make_float2(cr, ci);
        nr = tr * cr - ti * ci + v1.x; ni = tr * ci + ti * cr + v1.y; cr = nr; ci = ni;
        carry[(size_t)(jj + 2) * DD] = make_float2(cr, ci);
        nr = tr * cr - ti * ci + v2.x; ni = tr * ci + ti * cr + v2.y; cr = nr; ci = ni;
        carry[(size_t)(jj + 3) * DD] = make_float2(cr, ci);
        nr = tr * cr - ti * ci + v3.x; ni = tr * ci + ti * cr + v3.y; cr = nr; ci = ni;
        carry[(size_t)(jj + 4) * DD] = make_float2(cr, ci);
    }
    for (; jj < CC - 1; jj++) {
        float2 v = cv[(size_t)jj * DD];
        float nr = tr * cr - ti * ci + v.x;
        float ni = tr * ci + ti * cr + v.y;
        cr = nr; ci = ni;
        carry[(size_t)(jj + 1) * DD] = make_float2(cr, ci);
    }
}

// ---------------- fp16 tensor-core GEMM --------------------------------------
// C = A[M,K] @ W[K,N], fp16 in / fp32 accumulate.
// BM=BN=128, BK=32 (halfs); 128 threads = 4 warps (2x2), warp tile 64x64.
// ldmatrix.x4 for A, ldmatrix.x4.trans for B; mma.m16n8k16.
// Static smem 37.9KB, 2-stage cp.async pipeline.
// EPI 0: hid(half) = silu(acc+bias)
// EPI 1: out = conv * silu(acc+bias) + xres
// EPI 2: out = acc + bias + xres

constexpr int BKH = 32;              // halfs per k-tile
constexpr int ASH = 40;              // halfs per A row (32 + 8 pad -> 80B stride)
constexpr int BSH = 136;             // halfs per B row (128 + 8 pad -> 272B stride)
constexpr int ASTG = 128 * ASH;      // halfs per A stage
constexpr int BSTG = BKH * BSH;      // halfs per B stage

template <int EPI>
__device__ __forceinline__ void gemm_body(
    const __half* __restrict__ A, const __half* __restrict__ W,
    const float* __restrict__ bias, int N, int K,
    const float* __restrict__ conv, const float* __restrict__ xres,
    void* __restrict__ outp) {
    __shared__ __half Asm[2 * ASTG];
    __shared__ __half Bsm[2 * BSTG];
    uint32_t Asm_u = (uint32_t)__cvta_generic_to_shared(Asm);
    uint32_t Bsm_u = (uint32_t)__cvta_generic_to_shared(Bsm);

    int tid = threadIdx.x;
    int lane = tid & 31, wid = tid >> 5;
    int warp_m = wid >> 1;      // 0..1  (64-row slabs)
    int warp_n = wid & 1;       // 0..1  (64-col slabs)
    int grp = lane >> 2, tig = lane & 3;
    int bm = blockIdx.y, bn = blockIdx.x;

    // ldmatrix address components (canonical x4 grouping)
    int lm_row = (lane & 7) + (((lane >> 3) & 1) << 3);  // 0..15
    int lm_cg  = (lane >> 4) << 3;                        // 0 or 8

    float acc[4][8][4];
#pragma unroll
    for (int mt = 0; mt < 4; mt++)
#pragma unroll
        for (int nt = 0; nt < 8; nt++)
#pragma unroll
            for (int i = 0; i < 4; i++) acc[mt][nt][i] = 0.0f;

    const int ntiles = K / BKH;

    auto load_tile = [&](int kt, int s) {
        // A tile: 128 rows x 32 halfs = 512 x 16B chunks
#pragma unroll
        for (int i = 0; i < 4; i++) {
            int id = tid + i * 128;
            int r = id >> 2, c = id & 3;
            uint32_t dst = Asm_u + (uint32_t)((s * ASTG + r * ASH + c * 8) * 2);
            CP_ASYNC16(dst, A + (size_t)(bm * 128 + r) * K + kt + c * 8);
        }
        // B tile: 32 rows x 128 halfs = 512 x 16B chunks
#pragma unroll
        for (int i = 0; i < 4; i++) {
            int id = tid + i * 128;
            int r = id >> 4, c = id & 15;
            uint32_t dst = Bsm_u + (uint32_t)((s * BSTG + r * BSH + c * 8) * 2);
            CP_ASYNC16(dst, W + (size_t)(kt + r) * N + bn * 128 + c * 8);
        }
        CP_COMMIT();
    };

    load_tile(0, 0);

    for (int t = 0; t < ntiles; t++) {
        int s = t & 1;
        if (t + 1 < ntiles) {
            load_tile((t + 1) * BKH, s ^ 1);
            CP_WAIT(1);
        } else {
            CP_WAIT(0);
        }
        __syncthreads();

        uint32_t Abase = Asm_u + (uint32_t)(s * ASTG * 2);
        uint32_t Bbase = Bsm_u + (uint32_t)(s * BSTG * 2);
#pragma unroll
        for (int kk = 0; kk < BKH; kk += 16) {
            uint32_t af[4][4], bf[8][2];
#pragma unroll
            for (int mt = 0; mt < 4; mt++) {
                int row = warp_m * 64 + mt * 16 + lm_row;
                uint32_t addr = Abase + (uint32_t)((row * ASH + kk + lm_cg) * 2);
                LDMX4(af[mt][0], af[mt][1], af[mt][2], af[mt][3], addr);
            }
#pragma unroll
            for (int p = 0; p < 4; p++) {
                int krow = kk + lm_row;
                int col = warp_n * 64 + p * 16 + lm_cg;
                uint32_t addr = Bbase + (uint32_t)((krow * BSH + col) * 2);
                LDMX4T(bf[2 * p][0], bf[2 * p][1], bf[2 * p + 1][0], bf[2 * p + 1][1], addr);
            }
#pragma unroll
            for (int mt = 0; mt < 4; mt++)
#pragma unroll
                for (int nt = 0; nt < 8; nt++)
                    mma16(acc[mt][nt], af[mt], bf[nt]);
        }
        __syncthreads();
    }

    // ---- epilogue ----
#pragma unroll
    for (int mt = 0; mt < 4; mt++) {
#pragma unroll
        for (int nt = 0; nt < 8; nt++) {
            int r0 = bm * 128 + warp_m * 64 + mt * 16 + grp;
            int c0 = bn * 128 + warp_n * 64 + nt * 8 + 2 * tig;
#pragma unroll
            for (int half = 0; half < 2; half++) {
                int r = r0 + half * 8;
                float v0 = acc[mt][nt][half * 2 + 0];
                float v1 = acc[mt][nt][half * 2 + 1];
                float2 bs = *(const float2*)(bias + c0);
                v0 += bs.x; v1 += bs.y;
                size_t idx = (size_t)r * N + c0;
                if (EPI == 0) {
                    *(__half2*)((__half*)outp + idx) =
                        __floats2half2_rn(silu(v0), silu(v1));
                } else if (EPI == 1) {
                    float2 cv = *(const float2*)(conv + idx);
                    float2 xr = *(const float2*)(xres + idx);
                    float2 o;
                    o.x = cv.x * silu(v0) + xr.x;
                    o.y = cv.y * silu(v1) + xr.y;
                    *(float2*)((float*)outp + idx) = o;
                } else {
                    float2 xr = *(const float2*)(xres + idx);
                    float2 o;
                    o.x = v0 + xr.x;
                    o.y = v1 + xr.y;
                    *(float2*)((float*)outp + idx) = o;
                }
            }
        }
    }
}

__global__ void __launch_bounds__(128) k_gemm1(const float* __restrict__ x,
                                               const float* __restrict__ b) {
    gemm_body<1>(g_xh, g_fcwh, b, DD, DD, g_conv, x, g_x2);
}
__global__ void __launch_bounds__(128) k_gemm2(const float* __restrict__ b) {
    gemm_body<0>(g_x3h, g_w1h, b, FFD, DD, nullptr, nullptr, g_hidh);
}
__global__ void __launch_bounds__(128) k_gemm3(const float* __restrict__ b,
                                               float* __restrict__ out) {
    gemm_body<2>(g_hidh, g_w2h, b, DD, FFD, nullptr, g_x2, out);
}

// ---------------- launch -----------------------------------------------------
extern "C" void kernel_launch(void* const* d_in, const int* in_sizes, int n_in,
                              void* d_out, int out_size) {
    const float* x     = (const float*)d_in[0];
    const float* ln_g  = (const float*)d_in[1];
    const float* ln_b  = (const float*)d_in[2];
    const float* fc_w  = (const float*)d_in[3];
    const float* fc_b  = (const float*)d_in[4];
    const float* w1    = (const float*)d_in[5];
    const float* b1    = (const float*)d_in[6];
    const float* w2    = (const float*)d_in[7];
    const float* b2    = (const float*)d_in[8];
    const float* ph_re = (const float*)d_in[9];
    const float* ph_im = (const float*)d_in[10];
    const float* phi_re= (const float*)d_in[11];
    const float* phi_im= (const float*)d_in[12];
    const float* lci_re= (const float*)d_in[13];
    const float* lci_im= (const float*)d_in[14];
    float* out = (float*)d_out;

    // 0) convert weights to fp16 (rn)
    k_roundw<<<(DD * FFD / 4 + 255) / 256, 256>>>(fc_w, w1, w2);
    // 1) LN stats of x (+ fp16 x copy)
    k_stats1<<<MROWS, 256>>>(x);
    // 2-4) spiral conv scan
    k_scan<false><<<dim3(CC, BB), 1024>>>(x, ph_re, ph_im, phi_re, phi_im, ln_g, ln_b);
    k_scan2<<<(BB * DD) / 256, 256>>>(ph_re, ph_im, lci_re, lci_im);
    k_scan<true><<<dim3(CC, BB), 1024>>>(x, ph_re, ph_im, phi_re, phi_im, ln_g, ln_b);
    // 5) x2 = conv * silu(x@fc_w+fc_b) + x
    k_gemm1<<<dim3(DD / 128, MROWS / 128), 128>>>(x, fc_b);
    // 6) x3h = fp16(LN(x2))
    k_lnx<<<MROWS, 256>>>(ln_g, ln_b);
    // 7) hidh = fp16(silu(x3@w1 + b1))
    k_gemm2<<<dim3(FFD / 128, MROWS / 128), 128>>>(b1);
    // 8) out = x2 + hid@w2 + b2
    k_gemm3<<<dim3(DD / 128, MROWS / 128), 128>>>(b2, out);
}

// round 8
// speedup vs baseline: 1.9405x; 1.0371x over previous
#include <cuda_runtime.h>
#include <cuda_fp16.h>
#include <cstdint>

// Problem constants
constexpr int BB = 4;
constexpr int LL = 4096;
constexpr int DD = 1024;
constexpr int FFD = 2048;
constexpr int TT = 32;              // scan chunk length
constexpr int CC = LL / TT;         // 128 chunks
constexpr int NG = 16;              // chunk groups (8 chunks each)
constexpr int MROWS = BB * LL;      // 16384
constexpr float EPS = 1e-5f;

// ---------------- scratch (device globals; no runtime allocation) ----------
__device__ float  g_y   [BB * LL * DD];     // silu(x@fc_w+fc_b)
__device__ float  g_x2  [BB * LL * DD];
__device__ __half g_xh  [BB * LL * DD];
__device__ __half g_x3h [BB * LL * DD];
__device__ __half g_hidh[(size_t)BB * LL * FFD];
__device__ __half g_fcwh[DD * DD];
__device__ __half g_w1h [DD * FFD];
__device__ __half g_w2h [FFD * DD];
__device__ float2 g_st1 [BB * LL];
__device__ float2 g_cv  [BB * CC * DD];     // per-chunk local sums v_j
__device__ float2 g_lcl [BB * CC * DD];     // within-group zero-init prefixes l_j
__device__ float2 g_gl  [BB * NG * DD];     // group totals L_g
__device__ float2 g_gC  [BB * NG * DD];     // group-entry carries C_g

// ---------------- helpers ---------------------------------------------------
__device__ __forceinline__ float silu(float v) {
    return v / (1.0f + expf(-v));
}

__device__ __forceinline__ void mma16(float* c, const uint32_t* a, const uint32_t* b) {
    asm volatile(
        "mma.sync.aligned.m16n8k16.row.col.f32.f16.f16.f32 "
        "{%0,%1,%2,%3}, {%4,%5,%6,%7}, {%8,%9}, {%0,%1,%2,%3};\n"
        : "+f"(c[0]), "+f"(c[1]), "+f"(c[2]), "+f"(c[3])
        : "r"(a[0]), "r"(a[1]), "r"(a[2]), "r"(a[3]), "r"(b[0]), "r"(b[1]));
}

#define LDMX4(r0, r1, r2, r3, addr) \
    asm volatile("ldmatrix.sync.aligned.m8n8.x4.shared.b16 {%0,%1,%2,%3}, [%4];" \
                 : "=r"(r0), "=r"(r1), "=r"(r2), "=r"(r3) : "r"(addr))
#define LDMX4T(r0, r1, r2, r3, addr) \
    asm volatile("ldmatrix.sync.aligned.m8n8.x4.trans.shared.b16 {%0,%1,%2,%3}, [%4];" \
                 : "=r"(r0), "=r"(r1), "=r"(r2), "=r"(r3) : "r"(addr))

#define CP_ASYNC16(dst_u32, src_ptr) \
    asm volatile("cp.async.cg.shared.global [%0], [%1], 16;\n" :: "r"(dst_u32), "l"(src_ptr))
#define CP_COMMIT() asm volatile("cp.async.commit_group;\n" ::)
#define CP_WAIT(n)  asm volatile("cp.async.wait_group %0;\n" :: "n"(n))

// ---------------- weight conversion fp32 -> fp16 (rn) ------------------------
__global__ void k_roundw(const float* __restrict__ fcw, const float* __restrict__ w1,
                         const float* __restrict__ w2) {
    int i = blockIdx.x * blockDim.x + threadIdx.x;   // float4 index
    if (i < DD * DD / 4) {
        float4 v = ((const float4*)fcw)[i];
        ((__half2*)g_fcwh)[2 * i]     = __floats2half2_rn(v.x, v.y);
        ((__half2*)g_fcwh)[2 * i + 1] = __floats2half2_rn(v.z, v.w);
    }
    if (i < DD * FFD / 4) {
        float4 v = ((const float4*)w1)[i];
        ((__half2*)g_w1h)[2 * i]     = __floats2half2_rn(v.x, v.y);
        ((__half2*)g_w1h)[2 * i + 1] = __floats2half2_rn(v.z, v.w);
        float4 u = ((const float4*)w2)[i];
        ((__half2*)g_w2h)[2 * i]     = __floats2half2_rn(u.x, u.y);
        ((__half2*)g_w2h)[2 * i + 1] = __floats2half2_rn(u.z, u.w);
    }
}

// ---------------- LN row stats of x (+ fp16 copy of x for GEMM1 A) -----------
__global__ void k_stats1(const float* __restrict__ x) {
    int row = blockIdx.x;
    int tid = threadIdx.x;          // 256 threads, 4 floats each = 1024
    float4 v = *(const float4*)(x + (size_t)row * DD + tid * 4);
    __half* hp = g_xh + (size_t)row * DD + tid * 4;
    *(__half2*)(hp)     = __floats2half2_rn(v.x, v.y);
    *(__half2*)(hp + 2) = __floats2half2_rn(v.z, v.w);
    float s = v.x + v.y + v.z + v.w;
    float q = v.x * v.x + v.y * v.y + v.z * v.z + v.w * v.w;
#pragma unroll
    for (int o = 16; o; o >>= 1) {
        s += __shfl_xor_sync(0xffffffffu, s, o);
        q += __shfl_xor_sync(0xffffffffu, q, o);
    }
    __shared__ float2 ws[8];
    if ((tid & 31) == 0) ws[tid >> 5] = make_float2(s, q);
    __syncthreads();
    if (tid < 8) {
        float ss = ws[tid].x, qq = ws[tid].y;
#pragma unroll
        for (int o = 4; o; o >>= 1) {
            ss += __shfl_xor_sync(0xffu, ss, o);
            qq += __shfl_xor_sync(0xffu, qq, o);
        }
        if (tid == 0) {
            float mean = ss * (1.0f / DD);
            float var  = qq * (1.0f / DD) - mean * mean;
            g_st1[row] = make_float2(mean, rsqrtf(var + EPS));
        }
    }
}

// ---------------- fused LN: x3h = fp16(LayerNorm(x2)) ------------------------
__global__ void k_lnx(const float* __restrict__ lng, const float* __restrict__ lnb) {
    int row = blockIdx.x;
    int tid = threadIdx.x;
    float4 v = *(const float4*)(g_x2 + (size_t)row * DD + tid * 4);
    float s = v.x + v.y + v.z + v.w;
    float q = v.x * v.x + v.y * v.y + v.z * v.z + v.w * v.w;
#pragma unroll
    for (int o = 16; o; o >>= 1) {
        s += __shfl_xor_sync(0xffffffffu, s, o);
        q += __shfl_xor_sync(0xffffffffu, q, o);
    }
    __shared__ float2 ws[8];
    __shared__ float2 fin;
    if ((tid & 31) == 0) ws[tid >> 5] = make_float2(s, q);
    __syncthreads();
    if (tid == 0) {
        float ss = 0.0f, qq = 0.0f;
#pragma unroll
        for (int i = 0; i < 8; i++) { ss += ws[i].x; qq += ws[i].y; }
        float mean = ss * (1.0f / DD);
        float var  = qq * (1.0f / DD) - mean * mean;
        fin = make_float2(mean, rsqrtf(var + EPS));
    }
    __syncthreads();
    float mean = fin.x, rstd = fin.y;
    float4 gg = *(const float4*)(lng + tid * 4);
    float4 bb = *(const float4*)(lnb + tid * 4);
    __half* hp = g_x3h + (size_t)row * DD + tid * 4;
    *(__half2*)(hp)     = __floats2half2_rn((v.x - mean) * rstd * gg.x + bb.x,
                                            (v.y - mean) * rstd * gg.y + bb.y);
    *(__half2*)(hp + 2) = __floats2half2_rn((v.z - mean) * rstd * gg.z + bb.z,
                                            (v.w - mean) * rstd * gg.w + bb.w);
}

// ---------------- spiral-conv scan ------------------------------------------
// c[t] = phz*c[t-1] + phi*xn[t],  c[-1] = lci,  phz = ph/|ph| * exp(-|ph|)
// Phase F : per-chunk local sums v_j (zero init) -> g_cv
// Phase 2a: per-group (8 chunks) zero-init prefixes l_j -> g_lcl, totals L_g -> g_gl
// Phase 2b: serial scan over 16 groups with P^8 -> group-entry carries C_g -> g_gC
// Phase T : carry[j] = P^r * C_g + l_j, then stream conv and write x2 = conv*y + x

__global__ void __launch_bounds__(1024) k_scanF(
    const float* __restrict__ x,
    const float* __restrict__ phre, const float* __restrict__ phim,
    const float* __restrict__ phir, const float* __restrict__ phii,
    const float* __restrict__ lng,  const float* __restrict__ lnb) {
    int d = threadIdx.x;
    int j = blockIdx.x;
    int b = blockIdx.y;

    float pre = phre[d], pim = phim[d];
    float a  = sqrtf(pre * pre + pim * pim);
    float sc = expf(-a) / a;
    float pzr = pre * sc, pzi = pim * sc;
    float fr = phir[d], fi = phii[d];
    float g = lng[d], bbv = lnb[d];

    size_t rowbase = (size_t)b * LL + (size_t)j * TT;
    float cr = 0.0f, ci = 0.0f;
    const float* xp = x + rowbase * DD + d;
#pragma unroll 4
    for (int s = 0; s < TT; s++) {
        float2 st = g_st1[rowbase + s];
        float xv = xp[(size_t)s * DD];
        float xn = (xv - st.x) * st.y * g + bbv;
        float nr = cr * pzr - ci * pzi + fr * xn;
        float ni = cr * pzi + ci * pzr + fi * xn;
        cr = nr; ci = ni;
    }
    g_cv[((size_t)b * CC + j) * DD + d] = make_float2(cr, ci);
}

__global__ void k_scan2a(const float* __restrict__ phre, const float* __restrict__ phim) {
    int idx = blockIdx.x * blockDim.x + threadIdx.x;    // BB*NG*DD threads
    int b = idx / (NG * DD);
    int rem = idx % (NG * DD);
    int g = rem / DD, d = rem % DD;

    float pre = phre[d], pim = phim[d];
    float a  = sqrtf(pre * pre + pim * pim);
    float sc = expf(-a) / a;
    float tr = pre * sc, ti = pim * sc;
    // P = phz^TT (TT=32 -> 5 squarings)
#pragma unroll
    for (int i = 0; i < 5; i++) {
        float nr = tr * tr - ti * ti;
        ti = 2.0f * tr * ti;
        tr = nr;
    }
    const float2* cv = g_cv  + ((size_t)b * CC + g * 8) * DD + d;
    float2*       lc = g_lcl + ((size_t)b * CC + g * 8) * DD + d;
    float lr = 0.0f, li = 0.0f;
#pragma unroll
    for (int r = 0; r < 8; r++) {
        lc[(size_t)r * DD] = make_float2(lr, li);
        float2 v = cv[(size_t)r * DD];
        float nr = tr * lr - ti * li + v.x;
        float ni = tr * li + ti * lr + v.y;
        lr = nr; li = ni;
    }
    g_gl[((size_t)b * NG + g) * DD + d] = make_float2(lr, li);
}

__global__ void k_scan2b(const float* __restrict__ phre, const float* __restrict__ phim,
                         const float* __restrict__ lcire, const float* __restrict__ lciim) {
    int idx = blockIdx.x * blockDim.x + threadIdx.x;    // BB*DD threads
    int b = idx / DD, d = idx % DD;
    float pre = phre[d], pim = phim[d];
    float a  = sqrtf(pre * pre + pim * pim);
    float sc = expf(-a) / a;
    float tr = pre * sc, ti = pim * sc;
    // P8 = phz^256 -> 8 squarings
#pragma unroll
    for (int i = 0; i < 8; i++) {
        float nr = tr * tr - ti * ti;
        ti = 2.0f * tr * ti;
        tr = nr;
    }
    float cr = lcire[d], ci = lciim[d];
    const float2* gl = g_gl + (size_t)b * NG * DD + d;
    float2*       gC = g_gC + (size_t)b * NG * DD + d;
#pragma unroll
    for (int g = 0; g < NG; g += 4) {
        float2 v0 = gl[(size_t)(g + 0) * DD];
        float2 v1 = gl[(size_t)(g + 1) * DD];
        float2 v2 = gl[(size_t)(g + 2) * DD];
        float2 v3 = gl[(size_t)(g + 3) * DD];
        float nr, ni;
        gC[(size_t)(g + 0) * DD] = make_float2(cr, ci);
        nr = tr * cr - ti * ci + v0.x; ni = tr * ci + ti * cr + v0.y; cr = nr; ci = ni;
        gC[(size_t)(g + 1) * DD] = make_float2(cr, ci);
        nr = tr * cr - ti * ci + v1.x; ni = tr * ci + ti * cr + v1.y; cr = nr; ci = ni;
        gC[(size_t)(g + 2) * DD] = make_float2(cr, ci);
        nr = tr * cr - ti * ci + v2.x; ni = tr * ci + ti * cr + v2.y; cr = nr; ci = ni;
        gC[(size_t)(g + 3) * DD] = make_float2(cr, ci);
        nr = tr * cr - ti * ci + v3.x; ni = tr * ci + ti * cr + v3.y; cr = nr; ci = ni;
    }
}

__global__ void __launch_bounds__(1024) k_scanT(
    const float* __restrict__ x,
    const float* __restrict__ phre, const float* __restrict__ phim,
    const float* __restrict__ phir, const float* __restrict__ phii,
    const float* __restrict__ lng,  const float* __restrict__ lnb) {
    int d = threadIdx.x;
    int j = blockIdx.x;
    int b = blockIdx.y;
    int grpi = j >> 3, r = j & 7;

    float pre = phre[d], pim = phim[d];
    float a  = sqrtf(pre * pre + pim * pim);
    float sc = expf(-a) / a;
    float pzr = pre * sc, pzi = pim * sc;
    float fr = phir[d], fi = phii[d];
    float g = lng[d], bbv = lnb[d];

    // P = phz^TT; then P^r (r uniform per block, <= 7 complex mults)
    float Pr_ = pre * sc, Pi_ = pim * sc;
#pragma unroll
    for (int i = 0; i < 5; i++) {
        float nr = Pr_ * Pr_ - Pi_ * Pi_;
        Pi_ = 2.0f * Pr_ * Pi_;
        Pr_ = nr;
    }
    float pr = 1.0f, pi = 0.0f;
    for (int i = 0; i < r; i++) {
        float nr = pr * Pr_ - pi * Pi_;
        pi = pr * Pi_ + pi * Pr_;
        pr = nr;
    }
    float2 Cg = g_gC[((size_t)b * NG + grpi) * DD + d];
    float2 lj = g_lcl[((size_t)b * CC + j) * DD + d];
    float cr = pr * Cg.x - pi * Cg.y + lj.x;
    float ci = pr * Cg.y + pi * Cg.x + lj.y;

    size_t rowbase = (size_t)b * LL + (size_t)j * TT;
    const float* xp = x   + rowbase * DD + d;
    const float* yp = g_y + rowbase * DD + d;
    float*       op = g_x2 + rowbase * DD + d;
#pragma unroll 4
    for (int s = 0; s < TT; s++) {
        float2 st = g_st1[rowbase + s];
        float xv = xp[(size_t)s * DD];
        float xn = (xv - st.x) * st.y * g + bbv;
        float nr = cr * pzr - ci * pzi + fr * xn;
        float ni = cr * pzi + ci * pzr + fi * xn;
        cr = nr; ci = ni;
        op[(size_t)s * DD] = cr * yp[(size_t)s * DD] + xv;
    }
}

// ---------------- fp16 tensor-core GEMM --------------------------------------
// C = A[M,K] @ W[K,N], fp16 in / fp32 accumulate.
// BM=BN=128, BK=32 (halfs); 128 threads = 4 warps (2x2), warp tile 64x64.
// EPI 0: hid(half) = silu(acc+bias)
// EPI 2: out = acc + bias + xres
// EPI 3: y(fp32) = silu(acc+bias)

constexpr int BKH = 32;              // halfs per k-tile
constexpr int ASH = 40;              // halfs per A row (32 + 8 pad -> 80B stride)
constexpr int BSH = 136;             // halfs per B row (128 + 8 pad -> 272B stride)
constexpr int ASTG = 128 * ASH;      // halfs per A stage
constexpr int BSTG = BKH * BSH;      // halfs per B stage

template <int EPI>
__device__ __forceinline__ void gemm_body(
    const __half* __restrict__ A, const __half* __restrict__ W,
    const float* __restrict__ bias, int N, int K,
    const float* __restrict__ xres, void* __restrict__ outp) {
    __shared__ __half Asm[2 * ASTG];
    __shared__ __half Bsm[2 * BSTG];
    uint32_t Asm_u = (uint32_t)__cvta_generic_to_shared(Asm);
    uint32_t Bsm_u = (uint32_t)__cvta_generic_to_shared(Bsm);

    int tid = threadIdx.x;
    int lane = tid & 31, wid = tid >> 5;
    int warp_m = wid >> 1;      // 0..1  (64-row slabs)
    int warp_n = wid & 1;       // 0..1  (64-col slabs)
    int grp = lane >> 2, tig = lane & 3;
    int bm = blockIdx.y, bn = blockIdx.x;

    int lm_row = (lane & 7) + (((lane >> 3) & 1) << 3);  // 0..15
    int lm_cg  = (lane >> 4) << 3;                        // 0 or 8

    float acc[4][8][4];
#pragma unroll
    for (int mt = 0; mt < 4; mt++)
#pragma unroll
        for (int nt = 0; nt < 8; nt++)
#pragma unroll
            for (int i = 0; i < 4; i++) acc[mt][nt][i] = 0.0f;

    const int ntiles = K / BKH;

    auto load_tile = [&](int kt, int s) {
#pragma unroll
        for (int i = 0; i < 4; i++) {
            int id = tid + i * 128;
            int r = id >> 2, c = id & 3;
            uint32_t dst = Asm_u + (uint32_t)((s * ASTG + r * ASH + c * 8) * 2);
            CP_ASYNC16(dst, A + (size_t)(bm * 128 + r) * K + kt + c * 8);
        }
#pragma unroll
        for (int i = 0; i < 4; i++) {
            int id = tid + i * 128;
            int r = id >> 4, c = id & 15;
            uint32_t dst = Bsm_u + (uint32_t)((s * BSTG + r * BSH + c * 8) * 2);
            CP_ASYNC16(dst, W + (size_t)(kt + r) * N + bn * 128 + c * 8);
        }
        CP_COMMIT();
    };

    load_tile(0, 0);

    for (int t = 0; t < ntiles; t++) {
        int s = t & 1;
        if (t + 1 < ntiles) {
            load_tile((t + 1) * BKH, s ^ 1);
            CP_WAIT(1);
        } else {
            CP_WAIT(0);
        }
        __syncthreads();

        uint32_t Abase = Asm_u + (uint32_t)(s * ASTG * 2);
        uint32_t Bbase = Bsm_u + (uint32_t)(s * BSTG * 2);
#pragma unroll
        for (int kk = 0; kk < BKH; kk += 16) {
            uint32_t af[4][4], bf[8][2];
#pragma unroll
            for (int mt = 0; mt < 4; mt++) {
                int row = warp_m * 64 + mt * 16 + lm_row;
                uint32_t addr = Abase + (uint32_t)((row * ASH + kk + lm_cg) * 2);
                LDMX4(af[mt][0], af[mt][1], af[mt][2], af[mt][3], addr);
            }
#pragma unroll
            for (int p = 0; p < 4; p++) {
                int krow = kk + lm_row;
                int col = warp_n * 64 + p * 16 + lm_cg;
                uint32_t addr = Bbase + (uint32_t)((krow * BSH + col) * 2);
                LDMX4T(bf[2 * p][0], bf[2 * p][1], bf[2 * p + 1][0], bf[2 * p + 1][1], addr);
            }
#pragma unroll
            for (int mt = 0; mt < 4; mt++)
#pragma unroll
                for (int nt = 0; nt < 8; nt++)
                    mma16(acc[mt][nt], af[mt], bf[nt]);
        }
        __syncthreads();
    }

    // ---- epilogue ----
#pragma unroll
    for (int mt = 0; mt < 4; mt++) {
#pragma unroll
        for (int nt = 0; nt < 8; nt++) {
            int r0 = bm * 128 + warp_m * 64 + mt * 16 + grp;
            int c0 = bn * 128 + warp_n * 64 + nt * 8 + 2 * tig;
#pragma unroll
            for (int half = 0; half < 2; half++) {
                int r = r0 + half * 8;
                float v0 = acc[mt][nt][half * 2 + 0];
                float v1 = acc[mt][nt][half * 2 + 1];
                float2 bs = *(const float2*)(bias + c0);
                v0 += bs.x; v1 += bs.y;
                size_t idx = (size_t)r * N + c0;
                if (EPI == 0) {
                    *(__half2*)((__half*)outp + idx) =
                        __floats2half2_rn(silu(v0), silu(v1));
                } else if (EPI == 2) {
                    float2 xr = *(const float2*)(xres + idx);
                    float2 o;
                    o.x = v0 + xr.x;
                    o.y = v1 + xr.y;
                    *(float2*)((float*)outp + idx) = o;
                } else {
                    float2 o;
                    o.x = silu(v0); o.y = silu(v1);
                    *(float2*)((float*)outp + idx) = o;
                }
            }
        }
    }
}

__global__ void __launch_bounds__(128) k_gemm1(const float* __restrict__ b) {
    gemm_body<3>(g_xh, g_fcwh, b, DD, DD, nullptr, g_y);
}
__global__ void __launch_bounds__(128) k_gemm2(const float* __restrict__ b) {
    gemm_body<0>(g_x3h, g_w1h, b, FFD, DD, nullptr, g_hidh);
}
__global__ void __launch_bounds__(128) k_gemm3(const float* __restrict__ b,
                                               float* __restrict__ out) {
    gemm_body<2>(g_hidh, g_w2h, b, DD, FFD, g_x2, out);
}

// ---------------- launch -----------------------------------------------------
extern "C" void kernel_launch(void* const* d_in, const int* in_sizes, int n_in,
                              void* d_out, int out_size) {
    const float* x     = (const float*)d_in[0];
    const float* ln_g  = (const float*)d_in[1];
    const float* ln_b  = (const float*)d_in[2];
    const float* fc_w  = (const float*)d_in[3];
    const float* fc_b  = (const float*)d_in[4];
    const float* w1    = (const float*)d_in[5];
    const float* b1    = (const float*)d_in[6];
    const float* w2    = (const float*)d_in[7];
    const float* b2    = (const float*)d_in[8];
    const float* ph_re = (const float*)d_in[9];
    const float* ph_im = (const float*)d_in[10];
    const float* phi_re= (const float*)d_in[11];
    const float* phi_im= (const float*)d_in[12];
    const float* lci_re= (const float*)d_in[13];
    const float* lci_im= (const float*)d_in[14];
    float* out = (float*)d_out;

    // 0) convert weights to fp16 (rn)
    k_roundw<<<(DD * FFD / 4 + 255) / 256, 256>>>(fc_w, w1, w2);
    // 1) LN stats of x (+ fp16 x copy)
    k_stats1<<<MROWS, 256>>>(x);
    // 2) per-chunk local sums
    k_scanF<<<dim3(CC, BB), 1024>>>(x, ph_re, ph_im, phi_re, phi_im, ln_g, ln_b);
    // 3) two-level chunk combine
    k_scan2a<<<(BB * NG * DD) / 256, 256>>>(ph_re, ph_im);
    k_scan2b<<<(BB * DD) / 256, 256>>>(ph_re, ph_im, lci_re, lci_im);
    // 4) y = silu(x@fc_w + fc_b)
    k_gemm1<<<dim3(DD / 128, MROWS / 128), 128>>>(fc_b);
    // 5) x2 = conv * y + x  (conv streamed in registers)
    k_scanT<<<dim3(CC, BB), 1024>>>(x, ph_re, ph_im, phi_re, phi_im, ln_g, ln_b);
    // 6) x3h = fp16(LN(x2))
    k_lnx<<<MROWS, 256>>>(ln_g, ln_b);
    // 7) hidh = fp16(silu(x3@w1 + b1))
    k_gemm2<<<dim3(FFD / 128, MROWS / 128), 128>>>(b1);
    // 8) out = x2 + hid@w2 + b2
    k_gemm3<<<dim3(DD / 128, MROWS / 128), 128>>>(b2, out);
}

// round 11
// speedup vs baseline: 1.9838x; 1.0223x over previous
#include <cuda_runtime.h>
#include <cuda_fp16.h>
#include <cstdint>

// Problem constants
constexpr int BB = 4;
constexpr int LL = 4096;
constexpr int DD = 1024;
constexpr int FFD = 2048;
constexpr int TT = 32;              // scan chunk length
constexpr int CC = LL / TT;         // 128 chunks
constexpr int NG = 16;              // chunk groups (8 chunks each)
constexpr int MROWS = BB * LL;      // 16384
constexpr float EPS = 1e-5f;

// ---------------- scratch (device globals; no runtime allocation) ----------
__device__ float  g_y   [BB * LL * DD];     // silu(x@fc_w+fc_b)
__device__ float  g_x2  [BB * LL * DD];
__device__ __half g_xh  [BB * LL * DD];
__device__ __half g_x3h [BB * LL * DD];
__device__ __half g_hidh[(size_t)BB * LL * FFD];
__device__ __half g_fcwh[DD * DD];
__device__ __half g_w1h [DD * FFD];
__device__ __half g_w2h [FFD * DD];
__device__ float2 g_st1 [BB * LL];
__device__ float2 g_cv  [BB * CC * DD];     // per-chunk local sums v_j
__device__ float2 g_lcl [BB * CC * DD];     // within-group zero-init prefixes l_j
__device__ float2 g_gl  [BB * NG * DD];     // group totals L_g
__device__ float2 g_gC  [BB * NG * DD];     // group-entry carries C_g

// ---------------- helpers ---------------------------------------------------
__device__ __forceinline__ float silu(float v) {
    return v / (1.0f + expf(-v));
}

__device__ __forceinline__ void mma16(float* c, const uint32_t* a, const uint32_t* b) {
    asm volatile(
        "mma.sync.aligned.m16n8k16.row.col.f32.f16.f16.f32 "
        "{%0,%1,%2,%3}, {%4,%5,%6,%7}, {%8,%9}, {%0,%1,%2,%3};\n"
        : "+f"(c[0]), "+f"(c[1]), "+f"(c[2]), "+f"(c[3])
        : "r"(a[0]), "r"(a[1]), "r"(a[2]), "r"(a[3]), "r"(b[0]), "r"(b[1]));
}

#define LDMX4(r0, r1, r2, r3, addr) \
    asm volatile("ldmatrix.sync.aligned.m8n8.x4.shared.b16 {%0,%1,%2,%3}, [%4];" \
                 : "=r"(r0), "=r"(r1), "=r"(r2), "=r"(r3) : "r"(addr))
#define LDMX4T(r0, r1, r2, r3, addr) \
    asm volatile("ldmatrix.sync.aligned.m8n8.x4.trans.shared.b16 {%0,%1,%2,%3}, [%4];" \
                 : "=r"(r0), "=r"(r1), "=r"(r2), "=r"(r3) : "r"(addr))

#define CP_ASYNC16(dst_u32, src_ptr) \
    asm volatile("cp.async.cg.shared.global [%0], [%1], 16;\n" :: "r"(dst_u32), "l"(src_ptr))
#define CP_COMMIT() asm volatile("cp.async.commit_group;\n" ::)
#define CP_WAIT(n)  asm volatile("cp.async.wait_group %0;\n" :: "n"(n))

// ---------------- weight conversion fp32 -> fp16 (rn) ------------------------
__global__ void k_roundw(const float* __restrict__ fcw, const float* __restrict__ w1,
                         const float* __restrict__ w2) {
    int i = blockIdx.x * blockDim.x + threadIdx.x;   // float4 index
    if (i < DD * DD / 4) {
        float4 v = ((const float4*)fcw)[i];
        ((__half2*)g_fcwh)[2 * i]     = __floats2half2_rn(v.x, v.y);
        ((__half2*)g_fcwh)[2 * i + 1] = __floats2half2_rn(v.z, v.w);
    }
    if (i < DD * FFD / 4) {
        float4 v = ((const float4*)w1)[i];
        ((__half2*)g_w1h)[2 * i]     = __floats2half2_rn(v.x, v.y);
        ((__half2*)g_w1h)[2 * i + 1] = __floats2half2_rn(v.z, v.w);
        float4 u = ((const float4*)w2)[i];
        ((__half2*)g_w2h)[2 * i]     = __floats2half2_rn(u.x, u.y);
        ((__half2*)g_w2h)[2 * i + 1] = __floats2half2_rn(u.z, u.w);
    }
}

// ---------------- LN row stats of x (+ fp16 copy of x for GEMM1 A) -----------
__global__ void k_stats1(const float* __restrict__ x) {
    int row = blockIdx.x;
    int tid = threadIdx.x;          // 256 threads, 4 floats each = 1024
    float4 v = *(const float4*)(x + (size_t)row * DD + tid * 4);
    __half* hp = g_xh + (size_t)row * DD + tid * 4;
    *(__half2*)(hp)     = __floats2half2_rn(v.x, v.y);
    *(__half2*)(hp + 2) = __floats2half2_rn(v.z, v.w);
    float s = v.x + v.y + v.z + v.w;
    float q = v.x * v.x + v.y * v.y + v.z * v.z + v.w * v.w;
#pragma unroll
    for (int o = 16; o; o >>= 1) {
        s += __shfl_xor_sync(0xffffffffu, s, o);
        q += __shfl_xor_sync(0xffffffffu, q, o);
    }
    __shared__ float2 ws[8];
    if ((tid & 31) == 0) ws[tid >> 5] = make_float2(s, q);
    __syncthreads();
    if (tid < 8) {
        float ss = ws[tid].x, qq = ws[tid].y;
#pragma unroll
        for (int o = 4; o; o >>= 1) {
            ss += __shfl_xor_sync(0xffu, ss, o);
            qq += __shfl_xor_sync(0xffu, qq, o);
        }
        if (tid == 0) {
            float mean = ss * (1.0f / DD);
            float var  = qq * (1.0f / DD) - mean * mean;
            g_st1[row] = make_float2(mean, rsqrtf(var + EPS));
        }
    }
}

// ---------------- fused LN: x3h = fp16(LayerNorm(x2)) ------------------------
__global__ void k_lnx(const float* __restrict__ lng, const float* __restrict__ lnb) {
    int row = blockIdx.x;
    int tid = threadIdx.x;
    float4 v = *(const float4*)(g_x2 + (size_t)row * DD + tid * 4);
    float s = v.x + v.y + v.z + v.w;
    float q = v.x * v.x + v.y * v.y + v.z * v.z + v.w * v.w;
#pragma unroll
    for (int o = 16; o; o >>= 1) {
        s += __shfl_xor_sync(0xffffffffu, s, o);
        q += __shfl_xor_sync(0xffffffffu, q, o);
    }
    __shared__ float2 ws[8];
    __shared__ float2 fin;
    if ((tid & 31) == 0) ws[tid >> 5] = make_float2(s, q);
    __syncthreads();
    if (tid == 0) {
        float ss = 0.0f, qq = 0.0f;
#pragma unroll
        for (int i = 0; i < 8; i++) { ss += ws[i].x; qq += ws[i].y; }
        float mean = ss * (1.0f / DD);
        float var  = qq * (1.0f / DD) - mean * mean;
        fin = make_float2(mean, rsqrtf(var + EPS));
    }
    __syncthreads();
    float mean = fin.x, rstd = fin.y;
    float4 gg = *(const float4*)(lng + tid * 4);
    float4 bb = *(const float4*)(lnb + tid * 4);
    __half* hp = g_x3h + (size_t)row * DD + tid * 4;
    *(__half2*)(hp)     = __floats2half2_rn((v.x - mean) * rstd * gg.x + bb.x,
                                            (v.y - mean) * rstd * gg.y + bb.y);
    *(__half2*)(hp + 2) = __floats2half2_rn((v.z - mean) * rstd * gg.z + bb.z,
                                            (v.w - mean) * rstd * gg.w + bb.w);
}

// ---------------- spiral-conv scan ------------------------------------------
// c[t] = phz*c[t-1] + phi*xn[t],  c[-1] = lci,  phz = ph/|ph| * exp(-|ph|)
// Phase F : per-chunk local sums v_j (zero init) -> g_cv  [512 thr, 2 chunks/blk, 4 dims/thr]
// Phase 2a: per-group (8 chunks) zero-init prefixes l_j -> g_lcl, totals L_g -> g_gl
// Phase 2b: serial scan over 16 groups with P^8 -> group-entry carries C_g -> g_gC
// Phase T : carry[j] = P^r*C_g + l_j; stream conv; x2 = conv*y + x

__global__ void __launch_bounds__(512) k_scanF(
    const float* __restrict__ x,
    const float* __restrict__ phre, const float* __restrict__ phim,
    const float* __restrict__ phir, const float* __restrict__ phii,
    const float* __restrict__ lng,  const float* __restrict__ lnb) {
    int tid = threadIdx.x;
    int tq = tid >> 8;                 // sub-chunk 0..1
    int tl = tid & 255;
    int d4 = tl * 4;
    int j = blockIdx.x * 2 + tq;
    int b = blockIdx.y;

    float4 pre4 = *(const float4*)(phre + d4);
    float4 pim4 = *(const float4*)(phim + d4);
    float4 fr4  = *(const float4*)(phir + d4);
    float4 fi4  = *(const float4*)(phii + d4);
    float4 gg4  = *(const float4*)(lng + d4);
    float4 bb4  = *(const float4*)(lnb + d4);
    float prr[4] = {pre4.x, pre4.y, pre4.z, pre4.w};
    float pii[4] = {pim4.x, pim4.y, pim4.z, pim4.w};
    float frr[4] = {fr4.x, fr4.y, fr4.z, fr4.w};
    float fii[4] = {fi4.x, fi4.y, fi4.z, fi4.w};
    float gv [4] = {gg4.x, gg4.y, gg4.z, gg4.w};
    float bv [4] = {bb4.x, bb4.y, bb4.z, bb4.w};

    float pzr[4], pzi[4], cr[4], ci[4];
#pragma unroll
    for (int i = 0; i < 4; i++) {
        float a  = sqrtf(prr[i] * prr[i] + pii[i] * pii[i]);
        float sc = expf(-a) / a;
        pzr[i] = prr[i] * sc; pzi[i] = pii[i] * sc;
        cr[i] = 0.0f; ci[i] = 0.0f;
    }

    size_t rowbase = (size_t)b * LL + (size_t)j * TT;
    const float* xp = x + rowbase * DD + d4;
#pragma unroll 4
    for (int s = 0; s < TT; s++) {
        float2 st = g_st1[rowbase + s];
        float4 xv = *(const float4*)(xp + (size_t)s * DD);
        float xa[4] = {xv.x, xv.y, xv.z, xv.w};
#pragma unroll
        for (int i = 0; i < 4; i++) {
            float xn = (xa[i] - st.x) * st.y * gv[i] + bv[i];
            float nr = cr[i] * pzr[i] - ci[i] * pzi[i] + frr[i] * xn;
            float ni = cr[i] * pzi[i] + ci[i] * pzr[i] + fii[i] * xn;
            cr[i] = nr; ci[i] = ni;
        }
    }
    float2* dst = g_cv + ((size_t)b * CC + j) * DD + d4;
#pragma unroll
    for (int i = 0; i < 4; i++) dst[i] = make_float2(cr[i], ci[i]);
}

__global__ void k_scan2a(const float* __restrict__ phre, const float* __restrict__ phim) {
    int idx = blockIdx.x * blockDim.x + threadIdx.x;    // BB*NG*DD threads
    int b = idx / (NG * DD);
    int rem = idx % (NG * DD);
    int g = rem / DD, d = rem % DD;

    float pre = phre[d], pim = phim[d];
    float a  = sqrtf(pre * pre + pim * pim);
    float sc = expf(-a) / a;
    float tr = pre * sc, ti = pim * sc;
    // P = phz^TT (TT=32 -> 5 squarings)
#pragma unroll
    for (int i = 0; i < 5; i++) {
        float nr = tr * tr - ti * ti;
        ti = 2.0f * tr * ti;
        tr = nr;
    }
    const float2* cv = g_cv  + ((size_t)b * CC + g * 8) * DD + d;
    float2*       lc = g_lcl + ((size_t)b * CC + g * 8) * DD + d;
    float lr = 0.0f, li = 0.0f;
#pragma unroll
    for (int r = 0; r < 8; r++) {
        lc[(size_t)r * DD] = make_float2(lr, li);
        float2 v = cv[(size_t)r * DD];
        float nr = tr * lr - ti * li + v.x;
        float ni = tr * li + ti * lr + v.y;
        lr = nr; li = ni;
    }
    g_gl[((size_t)b * NG + g) * DD + d] = make_float2(lr, li);
}

__global__ void k_scan2b(const float* __restrict__ phre, const float* __restrict__ phim,
                         const float* __restrict__ lcire, const float* __restrict__ lciim) {
    int idx = blockIdx.x * blockDim.x + threadIdx.x;    // BB*DD threads
    int b = idx / DD, d = idx % DD;
    float pre = phre[d], pim = phim[d];
    float a  = sqrtf(pre * pre + pim * pim);
    float sc = expf(-a) / a;
    float tr = pre * sc, ti = pim * sc;
    // P8 = phz^256 -> 8 squarings
#pragma unroll
    for (int i = 0; i < 8; i++) {
        float nr = tr * tr - ti * ti;
        ti = 2.0f * tr * ti;
        tr = nr;
    }
    float cr = lcire[d], ci = lciim[d];
    const float2* gl = g_gl + (size_t)b * NG * DD + d;
    float2*       gC = g_gC + (size_t)b * NG * DD + d;
#pragma unroll
    for (int g = 0; g < NG; g += 4) {
        float2 v0 = gl[(size_t)(g + 0) * DD];
        float2 v1 = gl[(size_t)(g + 1) * DD];
        float2 v2 = gl[(size_t)(g + 2) * DD];
        float2 v3 = gl[(size_t)(g + 3) * DD];
        float nr, ni;
        gC[(size_t)(g + 0) * DD] = make_float2(cr, ci);
        nr = tr * cr - ti * ci + v0.x; ni = tr * ci + ti * cr + v0.y; cr = nr; ci = ni;
        gC[(size_t)(g + 1) * DD] = make_float2(cr, ci);
        nr = tr * cr - ti * ci + v1.x; ni = tr * ci + ti * cr + v1.y; cr = nr; ci = ni;
        gC[(size_t)(g + 2) * DD] = make_float2(cr, ci);
        nr = tr * cr - ti * ci + v2.x; ni = tr * ci + ti * cr + v2.y; cr = nr; ci = ni;
        gC[(size_t)(g + 3) * DD] = make_float2(cr, ci);
        nr = tr * cr - ti * ci + v3.x; ni = tr * ci + ti * cr + v3.y; cr = nr; ci = ni;
    }
}

// Phase T: carry reconstruction + conv stream + x2 = conv*y + x.
// 512 threads; 2 chunks/block, 4 dims/thread.
__global__ void __launch_bounds__(512) k_scanT(
    const float* __restrict__ x,
    const float* __restrict__ phre, const float* __restrict__ phim,
    const float* __restrict__ phir, const float* __restrict__ phii,
    const float* __restrict__ lng,  const float* __restrict__ lnb) {
    int tid = threadIdx.x;
    int tq = tid >> 8;
    int tl = tid & 255;
    int d4 = tl * 4;
    int j = blockIdx.x * 2 + tq;
    int b = blockIdx.y;
    int grpi = j >> 3, r = j & 7;

    float4 pre4 = *(const float4*)(phre + d4);
    float4 pim4 = *(const float4*)(phim + d4);
    float4 fr4  = *(const float4*)(phir + d4);
    float4 fi4  = *(const float4*)(phii + d4);
    float4 gg4  = *(const float4*)(lng + d4);
    float4 bb4  = *(const float4*)(lnb + d4);
    float prr[4] = {pre4.x, pre4.y, pre4.z, pre4.w};
    float pii[4] = {pim4.x, pim4.y, pim4.z, pim4.w};
    float frr[4] = {fr4.x, fr4.y, fr4.z, fr4.w};
    float fii[4] = {fi4.x, fi4.y, fi4.z, fi4.w};
    float gv [4] = {gg4.x, gg4.y, gg4.z, gg4.w};
    float bv [4] = {bb4.x, bb4.y, bb4.z, bb4.w};

    float pzr[4], pzi[4], cr[4], ci[4];
#pragma unroll
    for (int i = 0; i < 4; i++) {
        float a  = sqrtf(prr[i] * prr[i] + pii[i] * pii[i]);
        float sc = expf(-a) / a;
        pzr[i] = prr[i] * sc; pzi[i] = pii[i] * sc;
        // P = phz^TT; then P^r (r uniform across threads of a chunk)
        float Pr = pzr[i], Pi = pzi[i];
#pragma unroll
        for (int q = 0; q < 5; q++) {
            float nr = Pr * Pr - Pi * Pi;
            Pi = 2.0f * Pr * Pi;
            Pr = nr;
        }
        float pwr = 1.0f, pwi = 0.0f;
        for (int q = 0; q < r; q++) {
            float nr = pwr * Pr - pwi * Pi;
            pwi = pwr * Pi + pwi * Pr;
            pwr = nr;
        }
        float2 Cg = g_gC[((size_t)b * NG + grpi) * DD + d4 + i];
        float2 lj = g_lcl[((size_t)b * CC + j) * DD + d4 + i];
        cr[i] = pwr * Cg.x - pwi * Cg.y + lj.x;
        ci[i] = pwr * Cg.y + pwi * Cg.x + lj.y;
    }

    size_t rowbase = (size_t)b * LL + (size_t)j * TT;
    const float* xp = x    + rowbase * DD + d4;
    const float* yp = g_y  + rowbase * DD + d4;
    float*       op = g_x2 + rowbase * DD + d4;
#pragma unroll 4
    for (int s = 0; s < TT; s++) {
        float2 st = g_st1[rowbase + s];
        float4 xv = *(const float4*)(xp + (size_t)s * DD);
        float4 yv = *(const float4*)(yp + (size_t)s * DD);
        float xa[4] = {xv.x, xv.y, xv.z, xv.w};
        float ya[4] = {yv.x, yv.y, yv.z, yv.w};
        float oa[4];
#pragma unroll
        for (int i = 0; i < 4; i++) {
            float xn = (xa[i] - st.x) * st.y * gv[i] + bv[i];
            float nr = cr[i] * pzr[i] - ci[i] * pzi[i] + frr[i] * xn;
            float ni = cr[i] * pzi[i] + ci[i] * pzr[i] + fii[i] * xn;
            cr[i] = nr; ci[i] = ni;
            oa[i] = nr * ya[i] + xa[i];
        }
        float4 ov = make_float4(oa[0], oa[1], oa[2], oa[3]);
        *(float4*)(op + (size_t)s * DD) = ov;
    }
}

// ---------------- fp16 tensor-core GEMM --------------------------------------
// C = A[M,K] @ W[K,N], fp16 in / fp32 accumulate.
// BM=BN=128, BK=32 (halfs); 128 threads = 4 warps (2x2), warp tile 64x64.
// EPI 0: hid(half) = silu(acc+bias)
// EPI 2: out = acc + bias + xres
// EPI 3: y(fp32) = silu(acc+bias)

constexpr int BKH = 32;              // halfs per k-tile
constexpr int ASH = 40;              // halfs per A row (32 + 8 pad -> 80B stride)
constexpr int BSH = 136;             // halfs per B row (128 + 8 pad -> 272B stride)
constexpr int ASTG = 128 * ASH;      // halfs per A stage
constexpr int BSTG = BKH * BSH;      // halfs per B stage

template <int EPI>
__device__ __forceinline__ void gemm_body(
    const __half* __restrict__ A, const __half* __restrict__ W,
    const float* __restrict__ bias, int N, int K,
    const float* __restrict__ xres, void* __restrict__ outp) {
    __shared__ __half Asm[2 * ASTG];
    __shared__ __half Bsm[2 * BSTG];
    uint32_t Asm_u = (uint32_t)__cvta_generic_to_shared(Asm);
    uint32_t Bsm_u = (uint32_t)__cvta_generic_to_shared(Bsm);

    int tid = threadIdx.x;
    int lane = tid & 31, wid = tid >> 5;
    int warp_m = wid >> 1;      // 0..1  (64-row slabs)
    int warp_n = wid & 1;       // 0..1  (64-col slabs)
    int grp = lane >> 2, tig = lane & 3;
    int bm = blockIdx.y, bn = blockIdx.x;

    int lm_row = (lane & 7) + (((lane >> 3) & 1) << 3);  // 0..15
    int lm_cg  = (lane >> 4) << 3;                        // 0 or 8

    float acc[4][8][4];
#pragma unroll
    for (int mt = 0; mt < 4; mt++)
#pragma unroll
        for (int nt = 0; nt < 8; nt++)
#pragma unroll
            for (int i = 0; i < 4; i++) acc[mt][nt][i] = 0.0f;

    const int ntiles = K / BKH;

    auto load_tile = [&](int kt, int s) {
#pragma unroll
        for (int i = 0; i < 4; i++) {
            int id = tid + i * 128;
            int r = id >> 2, c = id & 3;
            uint32_t dst = Asm_u + (uint32_t)((s * ASTG + r * ASH + c * 8) * 2);
            CP_ASYNC16(dst, A + (size_t)(bm * 128 + r) * K + kt + c * 8);
        }
#pragma unroll
        for (int i = 0; i < 4; i++) {
            int id = tid + i * 128;
            int r = id >> 4, c = id & 15;
            uint32_t dst = Bsm_u + (uint32_t)((s * BSTG + r * BSH + c * 8) * 2);
            CP_ASYNC16(dst, W + (size_t)(kt + r) * N + bn * 128 + c * 8);
        }
        CP_COMMIT();
    };

    load_tile(0, 0);

    for (int t = 0; t < ntiles; t++) {
        int s = t & 1;
        if (t + 1 < ntiles) {
            load_tile((t + 1) * BKH, s ^ 1);
            CP_WAIT(1);
        } else {
            CP_WAIT(0);
        }
        __syncthreads();

        uint32_t Abase = Asm_u + (uint32_t)(s * ASTG * 2);
        uint32_t Bbase = Bsm_u + (uint32_t)(s * BSTG * 2);
#pragma unroll
        for (int kk = 0; kk < BKH; kk += 16) {
            uint32_t af[4][4], bf[8][2];
#pragma unroll
            for (int mt = 0; mt < 4; mt++) {
                int row = warp_m * 64 + mt * 16 + lm_row;
                uint32_t addr = Abase + (uint32_t)((row * ASH + kk + lm_cg) * 2);
                LDMX4(af[mt][0], af[mt][1], af[mt][2], af[mt][3], addr);
            }
#pragma unroll
            for (int p = 0; p < 4; p++) {
                int krow = kk + lm_row;
                int col = warp_n * 64 + p * 16 + lm_cg;
                uint32_t addr = Bbase + (uint32_t)((krow * BSH + col) * 2);
                LDMX4T(bf[2 * p][0], bf[2 * p][1], bf[2 * p + 1][0], bf[2 * p + 1][1], addr);
            }
#pragma unroll
            for (int mt = 0; mt < 4; mt++)
#pragma unroll
                for (int nt = 0; nt < 8; nt++)
                    mma16(acc[mt][nt], af[mt], bf[nt]);
        }
        __syncthreads();
    }

    // ---- epilogue ----
#pragma unroll
    for (int mt = 0; mt < 4; mt++) {
#pragma unroll
        for (int nt = 0; nt < 8; nt++) {
            int r0 = bm * 128 + warp_m * 64 + mt * 16 + grp;
            int c0 = bn * 128 + warp_n * 64 + nt * 8 + 2 * tig;
#pragma unroll
            for (int half = 0; half < 2; half++) {
                int r = r0 + half * 8;
                float v0 = acc[mt][nt][half * 2 + 0];
                float v1 = acc[mt][nt][half * 2 + 1];
                float2 bs = *(const float2*)(bias + c0);
                v0 += bs.x; v1 += bs.y;
                size_t idx = (size_t)r * N + c0;
                if (EPI == 0) {
                    *(__half2*)((__half*)outp + idx) =
                        __floats2half2_rn(silu(v0), silu(v1));
                } else if (EPI == 2) {
                    float2 xr = *(const float2*)(xres + idx);
                    float2 o;
                    o.x = v0 + xr.x;
                    o.y = v1 + xr.y;
                    *(float2*)((float*)outp + idx) = o;
                } else {
                    float2 o;
                    o.x = silu(v0); o.y = silu(v1);
                    *(float2*)((float*)outp + idx) = o;
                }
            }
        }
    }
}

__global__ void __launch_bounds__(128) k_gemm1(const float* __restrict__ b) {
    gemm_body<3>(g_xh, g_fcwh, b, DD, DD, nullptr, g_y);
}
__global__ void __launch_bounds__(128) k_gemm2(const float* __restrict__ b) {
    gemm_body<0>(g_x3h, g_w1h, b, FFD, DD, nullptr, g_hidh);
}
__global__ void __launch_bounds__(128) k_gemm3(const float* __restrict__ b,
                                               float* __restrict__ out) {
    gemm_body<2>(g_hidh, g_w2h, b, DD, FFD, g_x2, out);
}

// ---------------- launch -----------------------------------------------------
extern "C" void kernel_launch(void* const* d_in, const int* in_sizes, int n_in,
                              void* d_out, int out_size) {
    const float* x     = (const float*)d_in[0];
    const float* ln_g  = (const float*)d_in[1];
    const float* ln_b  = (const float*)d_in[2];
    const float* fc_w  = (const float*)d_in[3];
    const float* fc_b  = (const float*)d_in[4];
    const float* w1    = (const float*)d_in[5];
    const float* b1    = (const float*)d_in[6];
    const float* w2    = (const float*)d_in[7];
    const float* b2    = (const float*)d_in[8];
    const float* ph_re = (const float*)d_in[9];
    const float* ph_im = (const float*)d_in[10];
    const float* phi_re= (const float*)d_in[11];
    const float* phi_im= (const float*)d_in[12];
    const float* lci_re= (const float*)d_in[13];
    const float* lci_im= (const float*)d_in[14];
    float* out = (float*)d_out;

    // 0) convert weights to fp16 (rn)
    k_roundw<<<(DD * FFD / 4 + 255) / 256, 256>>>(fc_w, w1, w2);
    // 1) LN stats of x (+ fp16 x copy)
    k_stats1<<<MROWS, 256>>>(x);
    // 2) per-chunk local sums (2 chunks/block, 4 dims/thread)
    k_scanF<<<dim3(CC / 2, BB), 512>>>(x, ph_re, ph_im, phi_re, phi_im, ln_g, ln_b);
    // 3) two-level chunk combine
    k_scan2a<<<(BB * NG * DD) / 256, 256>>>(ph_re, ph_im);
    k_scan2b<<<(BB * DD) / 256, 256>>>(ph_re, ph_im, lci_re, lci_im);
    // 4) y = silu(x@fc_w + fc_b)
    k_gemm1<<<dim3(DD / 128, MROWS / 128), 128>>>(fc_b);
    // 5) x2 = conv*y + x  (conv streamed in registers)
    k_scanT<<<dim3(CC / 2, BB), 512>>>(x, ph_re, ph_im, phi_re, phi_im, ln_g, ln_b);
    // 6) x3h = fp16(LN(x2))
    k_lnx<<<MROWS, 256>>>(ln_g, ln_b);
    // 7) hidh = fp16(silu(x3@w1 + b1))
    k_gemm2<<<dim3(FFD / 128, MROWS / 128), 128>>>(b1);
    // 8) out = x2 + hid@w2 + b2
    k_gemm3<<<dim3(DD / 128, MROWS / 128), 128>>>(b2, out);
}

// round 14
// speedup vs baseline: 2.0145x; 1.0155x over previous
#include <cuda_runtime.h>
#include <cuda_fp16.h>
#include <cstdint>

// Problem constants
constexpr int BB = 4;
constexpr int LL = 4096;
constexpr int DD = 1024;
constexpr int FFD = 2048;
constexpr int TT = 32;              // scan chunk length
constexpr int CC = LL / TT;         // 128 chunks
constexpr int NG = 16;              // chunk groups (8 chunks each)
constexpr int MROWS = BB * LL;      // 16384
constexpr float EPS = 1e-5f;

// ---------------- scratch (device globals; no runtime allocation) ----------
__device__ __half g_yh  [BB * LL * DD];     // silu(x@fc_w+fc_b), fp16
__device__ float  g_x2  [BB * LL * DD];
__device__ __half g_xh  [BB * LL * DD];
__device__ __half g_x3h [BB * LL * DD];
__device__ __half g_hidh[(size_t)BB * LL * FFD];
__device__ __half g_fcwh[DD * DD];
__device__ __half g_w1h [DD * FFD];
__device__ __half g_w2h [FFD * DD];
__device__ float2 g_st1 [BB * LL];
__device__ float2 g_cv  [BB * CC * DD];     // per-chunk local sums v_j
__device__ float2 g_lcl [BB * CC * DD];     // within-group zero-init prefixes l_j
__device__ float2 g_gl  [BB * NG * DD];     // group totals L_g
__device__ float2 g_gC  [BB * NG * DD];     // group-entry carries C_g

// ---------------- helpers ---------------------------------------------------
__device__ __forceinline__ float silu(float v) {
    return v / (1.0f + expf(-v));
}

__device__ __forceinline__ void mma16(float* c, const uint32_t* a, const uint32_t* b) {
    asm volatile(
        "mma.sync.aligned.m16n8k16.row.col.f32.f16.f16.f32 "
        "{%0,%1,%2,%3}, {%4,%5,%6,%7}, {%8,%9}, {%0,%1,%2,%3};\n"
        : "+f"(c[0]), "+f"(c[1]), "+f"(c[2]), "+f"(c[3])
        : "r"(a[0]), "r"(a[1]), "r"(a[2]), "r"(a[3]), "r"(b[0]), "r"(b[1]));
}

#define LDMX4(r0, r1, r2, r3, addr) \
    asm volatile("ldmatrix.sync.aligned.m8n8.x4.shared.b16 {%0,%1,%2,%3}, [%4];" \
                 : "=r"(r0), "=r"(r1), "=r"(r2), "=r"(r3) : "r"(addr))
#define LDMX4T(r0, r1, r2, r3, addr) \
    asm volatile("ldmatrix.sync.aligned.m8n8.x4.trans.shared.b16 {%0,%1,%2,%3}, [%4];" \
                 : "=r"(r0), "=r"(r1), "=r"(r2), "=r"(r3) : "r"(addr))

#define CP_ASYNC16(dst_u32, src_ptr) \
    asm volatile("cp.async.cg.shared.global [%0], [%1], 16;\n" :: "r"(dst_u32), "l"(src_ptr))
#define CP_COMMIT() asm volatile("cp.async.commit_group;\n" ::)
#define CP_WAIT(n)  asm volatile("cp.async.wait_group %0;\n" :: "n"(n))

// ---------------- weight conversion fp32 -> fp16 (rn) ------------------------
__global__ void k_roundw(const float* __restrict__ fcw, const float* __restrict__ w1,
                         const float* __restrict__ w2) {
    int i = blockIdx.x * blockDim.x + threadIdx.x;   // float4 index
    if (i < DD * DD / 4) {
        float4 v = ((const float4*)fcw)[i];
        ((__half2*)g_fcwh)[2 * i]     = __floats2half2_rn(v.x, v.y);
        ((__half2*)g_fcwh)[2 * i + 1] = __floats2half2_rn(v.z, v.w);
    }
    if (i < DD * FFD / 4) {
        float4 v = ((const float4*)w1)[i];
        ((__half2*)g_w1h)[2 * i]     = __floats2half2_rn(v.x, v.y);
        ((__half2*)g_w1h)[2 * i + 1] = __floats2half2_rn(v.z, v.w);
        float4 u = ((const float4*)w2)[i];
        ((__half2*)g_w2h)[2 * i]     = __floats2half2_rn(u.x, u.y);
        ((__half2*)g_w2h)[2 * i + 1] = __floats2half2_rn(u.z, u.w);
    }
}

// ---------------- LN row stats of x (+ fp16 copy), warp-per-row --------------
// 512 threads = 16 warps; one warp per row; 8 float4 per lane. No smem/barrier.
__global__ void __launch_bounds__(512) k_stats1(const float* __restrict__ x) {
    int w = threadIdx.x >> 5, lane = threadIdx.x & 31;
    size_t row = (size_t)blockIdx.x * 16 + w;
    const float* xr = x + row * DD;
    __half* hp = g_xh + row * DD;
    float s = 0.0f, q = 0.0f;
#pragma unroll
    for (int k = 0; k < 8; k++) {
        int off = lane * 4 + k * 128;
        float4 v = *(const float4*)(xr + off);
        s += v.x + v.y + v.z + v.w;
        q += v.x * v.x + v.y * v.y + v.z * v.z + v.w * v.w;
        *(__half2*)(hp + off)     = __floats2half2_rn(v.x, v.y);
        *(__half2*)(hp + off + 2) = __floats2half2_rn(v.z, v.w);
    }
#pragma unroll
    for (int o = 16; o; o >>= 1) {
        s += __shfl_xor_sync(0xffffffffu, s, o);
        q += __shfl_xor_sync(0xffffffffu, q, o);
    }
    if (lane == 0) {
        float mean = s * (1.0f / DD);
        float var  = q * (1.0f / DD) - mean * mean;
        g_st1[row] = make_float2(mean, rsqrtf(var + EPS));
    }
}

// ---------------- x3h = fp16(LayerNorm(x2)), warp-per-row --------------------
__global__ void __launch_bounds__(512) k_lnx(const float* __restrict__ lng,
                                             const float* __restrict__ lnb) {
    int w = threadIdx.x >> 5, lane = threadIdx.x & 31;
    size_t row = (size_t)blockIdx.x * 16 + w;
    const float* xr = g_x2 + row * DD;
    float4 v[8];
    float s = 0.0f, q = 0.0f;
#pragma unroll
    for (int k = 0; k < 8; k++) {
        v[k] = *(const float4*)(xr + lane * 4 + k * 128);
        s += v[k].x + v[k].y + v[k].z + v[k].w;
        q += v[k].x * v[k].x + v[k].y * v[k].y + v[k].z * v[k].z + v[k].w * v[k].w;
    }
#pragma unroll
    for (int o = 16; o; o >>= 1) {
        s += __shfl_xor_sync(0xffffffffu, s, o);
        q += __shfl_xor_sync(0xffffffffu, q, o);
    }
    float mean = s * (1.0f / DD);
    float rstd = rsqrtf(q * (1.0f / DD) - mean * mean + EPS);
    __half* hp = g_x3h + row * DD;
#pragma unroll
    for (int k = 0; k < 8; k++) {
        int off = lane * 4 + k * 128;
        float4 gg = *(const float4*)(lng + off);
        float4 bb = *(const float4*)(lnb + off);
        *(__half2*)(hp + off) =
            __floats2half2_rn((v[k].x - mean) * rstd * gg.x + bb.x,
                              (v[k].y - mean) * rstd * gg.y + bb.y);
        *(__half2*)(hp + off + 2) =
            __floats2half2_rn((v[k].z - mean) * rstd * gg.z + bb.z,
                              (v[k].w - mean) * rstd * gg.w + bb.w);
    }
}

// ---------------- spiral-conv scan ------------------------------------------
// c[t] = phz*c[t-1] + phi*xn[t],  c[-1] = lci,  phz = ph/|ph| * exp(-|ph|)
// Phase F : per-chunk local sums v_j (zero init) -> g_cv  [512 thr, 2 chunks/blk, 4 dims/thr]
// Phase 2a: per-group (8 chunks) zero-init prefixes l_j -> g_lcl, totals L_g -> g_gl
// Phase 2b: serial scan over 16 groups with P^8 -> group-entry carries C_g -> g_gC
// Phase T : carry[j] = P^r*C_g + l_j; stream conv; x2 = conv*y + x

__global__ void __launch_bounds__(512) k_scanF(
    const float* __restrict__ x,
    const float* __restrict__ phre, const float* __restrict__ phim,
    const float* __restrict__ phir, const float* __restrict__ phii,
    const float* __restrict__ lng,  const float* __restrict__ lnb) {
    int tid = threadIdx.x;
    int tq = tid >> 8;                 // sub-chunk 0..1
    int tl = tid & 255;
    int d4 = tl * 4;
    int j = blockIdx.x * 2 + tq;
    int b = blockIdx.y;

    float4 pre4 = *(const float4*)(phre + d4);
    float4 pim4 = *(const float4*)(phim + d4);
    float4 fr4  = *(const float4*)(phir + d4);
    float4 fi4  = *(const float4*)(phii + d4);
    float4 gg4  = *(const float4*)(lng + d4);
    float4 bb4  = *(const float4*)(lnb + d4);
    float prr[4] = {pre4.x, pre4.y, pre4.z, pre4.w};
    float pii[4] = {pim4.x, pim4.y, pim4.z, pim4.w};
    float frr[4] = {fr4.x, fr4.y, fr4.z, fr4.w};
    float fii[4] = {fi4.x, fi4.y, fi4.z, fi4.w};
    float gv [4] = {gg4.x, gg4.y, gg4.z, gg4.w};
    float bv [4] = {bb4.x, bb4.y, bb4.z, bb4.w};

    float pzr[4], pzi[4], cr[4], ci[4];
#pragma unroll
    for (int i = 0; i < 4; i++) {
        float a  = sqrtf(prr[i] * prr[i] + pii[i] * pii[i]);
        float sc = expf(-a) / a;
        pzr[i] = prr[i] * sc; pzi[i] = pii[i] * sc;
        cr[i] = 0.0f; ci[i] = 0.0f;
    }

    size_t rowbase = (size_t)b * LL + (size_t)j * TT;
    const float* xp = x + rowbase * DD + d4;
#pragma unroll 4
    for (int s = 0; s < TT; s++) {
        float2 st = g_st1[rowbase + s];
        float4 xv = *(const float4*)(xp + (size_t)s * DD);
        float xa[4] = {xv.x, xv.y, xv.z, xv.w};
#pragma unroll
        for (int i = 0; i < 4; i++) {
            float xn = (xa[i] - st.x) * st.y * gv[i] + bv[i];
            float nr = cr[i] * pzr[i] - ci[i] * pzi[i] + frr[i] * xn;
            float ni = cr[i] * pzi[i] + ci[i] * pzr[i] + fii[i] * xn;
            cr[i] = nr; ci[i] = ni;
        }
    }
    float2* dst = g_cv + ((size_t)b * CC + j) * DD + d4;
#pragma unroll
    for (int i = 0; i < 4; i++) dst[i] = make_float2(cr[i], ci[i]);
}

__global__ void k_scan2a(const float* __restrict__ phre, const float* __restrict__ phim) {
    int idx = blockIdx.x * blockDim.x + threadIdx.x;    // BB*NG*DD threads
    int b = idx / (NG * DD);
    int rem = idx % (NG * DD);
    int g = rem / DD, d = rem % DD;

    float pre = phre[d], pim = phim[d];
    float a  = sqrtf(pre * pre + pim * pim);
    float sc = expf(-a) / a;
    float tr = pre * sc, ti = pim * sc;
    // P = phz^TT (TT=32 -> 5 squarings)
#pragma unroll
    for (int i = 0; i < 5; i++) {
        float nr = tr * tr - ti * ti;
        ti = 2.0f * tr * ti;
        tr = nr;
    }
    const float2* cv = g_cv  + ((size_t)b * CC + g * 8) * DD + d;
    float2*       lc = g_lcl + ((size_t)b * CC + g * 8) * DD + d;
    float lr = 0.0f, li = 0.0f;
#pragma unroll
    for (int r = 0; r < 8; r++) {
        lc[(size_t)r * DD] = make_float2(lr, li);
        float2 v = cv[(size_t)r * DD];
        float nr = tr * lr - ti * li + v.x;
        float ni = tr * li + ti * lr + v.y;
        lr = nr; li = ni;
    }
    g_gl[((size_t)b * NG + g) * DD + d] = make_float2(lr, li);
}

__global__ void k_scan2b(const float* __restrict__ phre, const float* __restrict__ phim,
                         const float* __restrict__ lcire, const float* __restrict__ lciim) {
    int idx = blockIdx.x * blockDim.x + threadIdx.x;    // BB*DD threads
    int b = idx / DD, d = idx % DD;
    float pre = phre[d], pim = phim[d];
    float a  = sqrtf(pre * pre + pim * pim);
    float sc = expf(-a) / a;
    float tr = pre * sc, ti = pim * sc;
    // P8 = phz^256 -> 8 squarings
#pragma unroll
    for (int i = 0; i < 8; i++) {
        float nr = tr * tr - ti * ti;
        ti = 2.0f * tr * ti;
        tr = nr;
    }
    float cr = lcire[d], ci = lciim[d];
    const float2* gl = g_gl + (size_t)b * NG * DD + d;
    float2*       gC = g_gC + (size_t)b * NG * DD + d;
#pragma unroll
    for (int g = 0; g < NG; g += 4) {
        float2 v0 = gl[(size_t)(g + 0) * DD];
        float2 v1 = gl[(size_t)(g + 1) * DD];
        float2 v2 = gl[(size_t)(g + 2) * DD];
        float2 v3 = gl[(size_t)(g + 3) * DD];
        float nr, ni;
        gC[(size_t)(g + 0) * DD] = make_float2(cr, ci);
        nr = tr * cr - ti * ci + v0.x; ni = tr * ci + ti * cr + v0.y; cr = nr; ci = ni;
        gC[(size_t)(g + 1) * DD] = make_float2(cr, ci);
        nr = tr * cr - ti * ci + v1.x; ni = tr * ci + ti * cr + v1.y; cr = nr; ci = ni;
        gC[(size_t)(g + 2) * DD] = make_float2(cr, ci);
        nr = tr * cr - ti * ci + v2.x; ni = tr * ci + ti * cr + v2.y; cr = nr; ci = ni;
        gC[(size_t)(g + 3) * DD] = make_float2(cr, ci);
        nr = tr * cr - ti * ci + v3.x; ni = tr * ci + ti * cr + v3.y; cr = nr; ci = ni;
    }
}

// Phase T: carry reconstruction + conv stream + x2 = conv*y + x.
// 512 threads; 2 chunks/block, 4 dims/thread; y read as fp16.
__global__ void __launch_bounds__(512) k_scanT(
    const float* __restrict__ x,
    const float* __restrict__ phre, const float* __restrict__ phim,
    const float* __restrict__ phir, const float* __restrict__ phii,
    const float* __restrict__ lng,  const float* __restrict__ lnb) {
    int tid = threadIdx.x;
    int tq = tid >> 8;
    int tl = tid & 255;
    int d4 = tl * 4;
    int j = blockIdx.x * 2 + tq;
    int b = blockIdx.y;
    int grpi = j >> 3, r = j & 7;

    float4 pre4 = *(const float4*)(phre + d4);
    float4 pim4 = *(const float4*)(phim + d4);
    float4 fr4  = *(const float4*)(phir + d4);
    float4 fi4  = *(const float4*)(phii + d4);
    float4 gg4  = *(const float4*)(lng + d4);
    float4 bb4  = *(const float4*)(lnb + d4);
    float prr[4] = {pre4.x, pre4.y, pre4.z, pre4.w};
    float pii[4] = {pim4.x, pim4.y, pim4.z, pim4.w};
    float frr[4] = {fr4.x, fr4.y, fr4.z, fr4.w};
    float fii[4] = {fi4.x, fi4.y, fi4.z, fi4.w};
    float gv [4] = {gg4.x, gg4.y, gg4.z, gg4.w};
    float bv [4] = {bb4.x, bb4.y, bb4.z, bb4.w};

    float pzr[4], pzi[4], cr[4], ci[4];
#pragma unroll
    for (int i = 0; i < 4; i++) {
        float a  = sqrtf(prr[i] * prr[i] + pii[i] * pii[i]);
        float sc = expf(-a) / a;
        pzr[i] = prr[i] * sc; pzi[i] = pii[i] * sc;
        // P = phz^TT; then P^r (r uniform across threads of a chunk)
        float Pr = pzr[i], Pi = pzi[i];
#pragma unroll
        for (int q = 0; q < 5; q++) {
            float nr = Pr * Pr - Pi * Pi;
            Pi = 2.0f * Pr * Pi;
            Pr = nr;
        }
        float pwr = 1.0f, pwi = 0.0f;
        for (int q = 0; q < r; q++) {
            float nr = pwr * Pr - pwi * Pi;
            pwi = pwr * Pi + pwi * Pr;
            pwr = nr;
        }
        float2 Cg = g_gC[((size_t)b * NG + grpi) * DD + d4 + i];
        float2 lj = g_lcl[((size_t)b * CC + j) * DD + d4 + i];
        cr[i] = pwr * Cg.x - pwi * Cg.y + lj.x;
        ci[i] = pwr * Cg.y + pwi * Cg.x + lj.y;
    }

    size_t rowbase = (size_t)b * LL + (size_t)j * TT;
    const float*  xp = x    + rowbase * DD + d4;
    const __half* yp = g_yh + rowbase * DD + d4;
    float*        op = g_x2 + rowbase * DD + d4;
#pragma unroll 4
    for (int s = 0; s < TT; s++) {
        float2 st = g_st1[rowbase + s];
        float4 xv = *(const float4*)(xp + (size_t)s * DD);
        __half2 yv0 = *(const __half2*)(yp + (size_t)s * DD);
        __half2 yv1 = *(const __half2*)(yp + (size_t)s * DD + 2);
        float2 yf0 = __half22float2(yv0);
        float2 yf1 = __half22float2(yv1);
        float xa[4] = {xv.x, xv.y, xv.z, xv.w};
        float ya[4] = {yf0.x, yf0.y, yf1.x, yf1.y};
        float oa[4];
#pragma unroll
        for (int i = 0; i < 4; i++) {
            float xn = (xa[i] - st.x) * st.y * gv[i] + bv[i];
            float nr = cr[i] * pzr[i] - ci[i] * pzi[i] + frr[i] * xn;
            float ni = cr[i] * pzi[i] + ci[i] * pzr[i] + fii[i] * xn;
            cr[i] = nr; ci[i] = ni;
            oa[i] = nr * ya[i] + xa[i];
        }
        float4 ov = make_float4(oa[0], oa[1], oa[2], oa[3]);
        *(float4*)(op + (size_t)s * DD) = ov;
    }
}

// ---------------- fp16 tensor-core GEMM --------------------------------------
// C = A[M,K] @ W[K,N], fp16 in / fp32 accumulate.
// BM=BN=128, BK=32 (halfs); 128 threads = 4 warps (2x2), warp tile 64x64.
// EPI 0: hid(half) = silu(acc+bias)
// EPI 2: out = acc + bias + xres
// EPI 3: y(half) = silu(acc+bias)

constexpr int BKH = 32;              // halfs per k-tile
constexpr int ASH = 40;              // halfs per A row (32 + 8 pad -> 80B stride)
constexpr int BSH = 136;             // halfs per B row (128 + 8 pad -> 272B stride)
constexpr int ASTG = 128 * ASH;      // halfs per A stage
constexpr int BSTG = BKH * BSH;      // halfs per B stage

template <int EPI>
__device__ __forceinline__ void gemm_body(
    const __half* __restrict__ A, const __half* __restrict__ W,
    const float* __restrict__ bias, int N, int K,
    const float* __restrict__ xres, void* __restrict__ outp) {
    __shared__ __half Asm[2 * ASTG];
    __shared__ __half Bsm[2 * BSTG];
    uint32_t Asm_u = (uint32_t)__cvta_generic_to_shared(Asm);
    uint32_t Bsm_u = (uint32_t)__cvta_generic_to_shared(Bsm);

    int tid = threadIdx.x;
    int lane = tid & 31, wid = tid >> 5;
    int warp_m = wid >> 1;      // 0..1  (64-row slabs)
    int warp_n = wid & 1;       // 0..1  (64-col slabs)
    int grp = lane >> 2, tig = lane & 3;
    int bm = blockIdx.y, bn = blockIdx.x;

    int lm_row = (lane & 7) + (((lane >> 3) & 1) << 3);  // 0..15
    int lm_cg  = (lane >> 4) << 3;                        // 0 or 8

    float acc[4][8][4];
#pragma unroll
    for (int mt = 0; mt < 4; mt++)
#pragma unroll
        for (int nt = 0; nt < 8; nt++)
#pragma unroll
            for (int i = 0; i < 4; i++) acc[mt][nt][i] = 0.0f;

    const int ntiles = K / BKH;

    auto load_tile = [&](int kt, int s) {
#pragma unroll
        for (int i = 0; i < 4; i++) {
            int id = tid + i * 128;
            int r = id >> 2, c = id & 3;
            uint32_t dst = Asm_u + (uint32_t)((s * ASTG + r * ASH + c * 8) * 2);
            CP_ASYNC16(dst, A + (size_t)(bm * 128 + r) * K + kt + c * 8);
        }
#pragma unroll
        for (int i = 0; i < 4; i++) {
            int id = tid + i * 128;
            int r = id >> 4, c = id & 15;
            uint32_t dst = Bsm_u + (uint32_t)((s * BSTG + r * BSH + c * 8) * 2);
            CP_ASYNC16(dst, W + (size_t)(kt + r) * N + bn * 128 + c * 8);
        }
        CP_COMMIT();
    };

    load_tile(0, 0);

    for (int t = 0; t < ntiles; t++) {
        int s = t & 1;
        if (t + 1 < ntiles) {
            load_tile((t + 1) * BKH, s ^ 1);
            CP_WAIT(1);
        } else {
            CP_WAIT(0);
        }
        __syncthreads();

        uint32_t Abase = Asm_u + (uint32_t)(s * ASTG * 2);
        uint32_t Bbase = Bsm_u + (uint32_t)(s * BSTG * 2);
#pragma unroll
        for (int kk = 0; kk < BKH; kk += 16) {
            uint32_t af[4][4], bf[8][2];
#pragma unroll
            for (int mt = 0; mt < 4; mt++) {
                int row = warp_m * 64 + mt * 16 + lm_row;
                uint32_t addr = Abase + (uint32_t)((row * ASH + kk + lm_cg) * 2);
                LDMX4(af[mt][0], af[mt][1], af[mt][2], af[mt][3], addr);
            }
#pragma unroll
            for (int p = 0; p < 4; p++) {
                int krow = kk + lm_row;
                int col = warp_n * 64 + p * 16 + lm_cg;
                uint32_t addr = Bbase + (uint32_t)((krow * BSH + col) * 2);
                LDMX4T(bf[2 * p][0], bf[2 * p][1], bf[2 * p + 1][0], bf[2 * p + 1][1], addr);
            }
#pragma unroll
            for (int mt = 0; mt < 4; mt++)
#pragma unroll
                for (int nt = 0; nt < 8; nt++)
                    mma16(acc[mt][nt], af[mt], bf[nt]);
        }
        __syncthreads();
    }

    // ---- epilogue ----
#pragma unroll
    for (int mt = 0; mt < 4; mt++) {
#pragma unroll
        for (int nt = 0; nt < 8; nt++) {
            int r0 = bm * 128 + warp_m * 64 + mt * 16 + grp;
            int c0 = bn * 128 + warp_n * 64 + nt * 8 + 2 * tig;
#pragma unroll
            for (int half = 0; half < 2; half++) {
                int r = r0 + half * 8;
                float v0 = acc[mt][nt][half * 2 + 0];
                float v1 = acc[mt][nt][half * 2 + 1];
                float2 bs = *(const float2*)(bias + c0);
                v0 += bs.x; v1 += bs.y;
                size_t idx = (size_t)r * N + c0;
                if (EPI == 0) {
                    *(__half2*)((__half*)outp + idx) =
                        __floats2half2_rn(silu(v0), silu(v1));
                } else if (EPI == 2) {
                    float2 xr = *(const float2*)(xres + idx);
                    float2 o;
                    o.x = v0 + xr.x;
                    o.y = v1 + xr.y;
                    *(float2*)((float*)outp + idx) = o;
                } else {
                    *(__half2*)((__half*)outp + idx) =
                        __floats2half2_rn(silu(v0), silu(v1));
                }
            }
        }
    }
}

__global__ void __launch_bounds__(128) k_gemm1(const float* __restrict__ b) {
    gemm_body<3>(g_xh, g_fcwh, b, DD, DD, nullptr, g_yh);
}
__global__ void __launch_bounds__(128) k_gemm2(const float* __restrict__ b) {
    gemm_body<0>(g_x3h, g_w1h, b, FFD, DD, nullptr, g_hidh);
}
__global__ void __launch_bounds__(128) k_gemm3(const float* __restrict__ b,
                                               float* __restrict__ out) {
    gemm_body<2>(g_hidh, g_w2h, b, DD, FFD, g_x2, out);
}

// ---------------- launch -----------------------------------------------------
extern "C" void kernel_launch(void* const* d_in, const int* in_sizes, int n_in,
                              void* d_out, int out_size) {
    const float* x     = (const float*)d_in[0];
    const float* ln_g  = (const float*)d_in[1];
    const float* ln_b  = (const float*)d_in[2];
    const float* fc_w  = (const float*)d_in[3];
    const float* fc_b  = (const float*)d_in[4];
    const float* w1    = (const float*)d_in[5];
    const float* b1    = (const float*)d_in[6];
    const float* w2    = (const float*)d_in[7];
    const float* b2    = (const float*)d_in[8];
    const float* ph_re = (const float*)d_in[9];
    const float* ph_im = (const float*)d_in[10];
    const float* phi_re= (const float*)d_in[11];
    const float* phi_im= (const float*)d_in[12];
    const float* lci_re= (const float*)d_in[13];
    const float* lci_im= (const float*)d_in[14];
    float* out = (float*)d_out;

    // 0) convert weights to fp16 (rn)
    k_roundw<<<(DD * FFD / 4 + 255) / 256, 256>>>(fc_w, w1, w2);
    // 1) LN stats of x (+ fp16 x copy), warp-per-row
    k_stats1<<<MROWS / 16, 512>>>(x);
    // 2) per-chunk local sums (2 chunks/block, 4 dims/thread)
    k_scanF<<<dim3(CC / 2, BB), 512>>>(x, ph_re, ph_im, phi_re, phi_im, ln_g, ln_b);
    // 3) two-level chunk combine
    k_scan2a<<<(BB * NG * DD) / 256, 256>>>(ph_re, ph_im);
    k_scan2b<<<(BB * DD) / 256, 256>>>(ph_re, ph_im, lci_re, lci_im);
    // 4) yh = fp16(silu(x@fc_w + fc_b))
    k_gemm1<<<dim3(DD / 128, MROWS / 128), 128>>>(fc_b);
    // 5) x2 = conv*yh + x  (conv streamed in registers)
    k_scanT<<<dim3(CC / 2, BB), 512>>>(x, ph_re, ph_im, phi_re, phi_im, ln_g, ln_b);
    // 6) x3h = fp16(LN(x2)), warp-per-row
    k_lnx<<<MROWS / 16, 512>>>(ln_g, ln_b);
    // 7) hidh = fp16(silu(x3@w1 + b1))
    k_gemm2<<<dim3(FFD / 128, MROWS / 128), 128>>>(b1);
    // 8) out = x2 + hid@w2 + b2
    k_gemm3<<<dim3(DD / 128, MROWS / 128), 128>>>(b2, out);
}